// round 9
// baseline (speedup 1.0000x reference)
#include <cuda_runtime.h>
#include <cuda_bf16.h>
#include <mma.h>
#include <stdint.h>

using namespace nvcuda;

#define NN 100000
#define NE 1600000
#define DH 128
#define NTILES 782   // ceil(NN/128)

// ---- scratch (device globals; no allocation allowed) ----
__device__ int   g_deg[NN];
__device__ int   g_rowptr[NN + 1];
__device__ int   g_cursor[NN];
__device__ uint2 g_csr[NE];                      // (src, w-bits) packed
__device__ __nv_bfloat16 g_agghi[NN * DH];
__device__ __nv_bfloat16 g_agglo[NN * DH];
__device__ __nv_bfloat16 g_xhi[NN * DH];
__device__ __nv_bfloat16 g_xlo[NN * DH];
__device__ __nv_bfloat16 g_h1hi[NN * DH];
__device__ __nv_bfloat16 g_h1lo[NN * DH];
__device__ __nv_bfloat16 g_h2hi[NN * DH];
__device__ __nv_bfloat16 g_h2lo[NN * DH];
__device__ float g_tail[128 * DH];
__device__ __nv_bfloat16 g_whi[3 * 256 * 128];   // [layer][k][n] : k<128 Wrel, k>=128 Wroot
__device__ __nv_bfloat16 g_wlo[3 * 256 * 128];

// ============ small helpers ============
__device__ __forceinline__ uint32_t bfpack(__nv_bfloat16 a, __nv_bfloat16 b) {
    return (uint32_t)__bfloat16_as_ushort(a) | ((uint32_t)__bfloat16_as_ushort(b) << 16);
}
__device__ __forceinline__ void split_bf(float v, __nv_bfloat16& h, __nv_bfloat16& l) {
    h = __float2bfloat16_rn(v);
    l = __float2bfloat16_rn(v - __bfloat162float(h));
}
__device__ __forceinline__ float2 bf2f2(uint32_t u) {
    __nv_bfloat162 b = *reinterpret_cast<__nv_bfloat162*>(&u);
    return __bfloat1622float2(b);
}

// ============ CSR build ============
__global__ void deg_count_kernel(const int* __restrict__ dst, int* __restrict__ deg) {
    int i = blockIdx.x * blockDim.x + threadIdx.x;
    if (i < NE) atomicAdd(&deg[dst[i]], 1);
}

__global__ void scan_kernel(const int* __restrict__ deg,
                            int* __restrict__ rowptr, int* __restrict__ cursor) {
    __shared__ int wsum[32];
    __shared__ int carry;
    const int tid = threadIdx.x, lane = tid & 31, warp = tid >> 5;
    if (tid == 0) carry = 0;
    __syncthreads();
    for (int base = 0; base < NN; base += 1024) {
        int i = base + tid;
        int v = (i < NN) ? deg[i] : 0;
        int s = v;
        #pragma unroll
        for (int off = 1; off < 32; off <<= 1) {
            int t = __shfl_up_sync(0xFFFFFFFF, s, off);
            if (lane >= off) s += t;
        }
        if (lane == 31) wsum[warp] = s;
        __syncthreads();
        if (warp == 0) {
            int w = wsum[lane];
            #pragma unroll
            for (int off = 1; off < 32; off <<= 1) {
                int t = __shfl_up_sync(0xFFFFFFFF, w, off);
                if (lane >= off) w += t;
            }
            wsum[lane] = w;
        }
        __syncthreads();
        int excl = s - v + (warp > 0 ? wsum[warp - 1] : 0) + carry;
        if (i < NN) { rowptr[i] = excl; cursor[i] = excl; }
        __syncthreads();
        if (tid == 0) carry += wsum[31];
        __syncthreads();
    }
    if (threadIdx.x == 0) rowptr[NN] = carry;
}

__global__ void fill_csr_kernel(const int* __restrict__ src, const int* __restrict__ dst,
                                const float* __restrict__ w, int* __restrict__ cursor,
                                uint2* __restrict__ csr) {
    int e = blockIdx.x * blockDim.x + threadIdx.x;
    if (e < NE) {
        int d = dst[e];
        int p = atomicAdd(&cursor[d], 1);
        csr[p] = make_uint2((unsigned)src[e], __float_as_uint(w[e]));
    }
}

// ============ x split (once) ============
__global__ void split_x_kernel(const float* __restrict__ x,
                               __nv_bfloat16* __restrict__ hi, __nv_bfloat16* __restrict__ lo) {
    int i = blockIdx.x * blockDim.x + threadIdx.x;   // per 4 elems
    if (i >= NN * DH / 4) return;
    float4 v = *reinterpret_cast<const float4*>(x + (size_t)i * 4);
    __nv_bfloat16 h0, l0, h1, l1, h2, l2, h3, l3;
    split_bf(v.x, h0, l0); split_bf(v.y, h1, l1);
    split_bf(v.z, h2, l2); split_bf(v.w, h3, l3);
    *reinterpret_cast<uint2*>(hi + (size_t)i * 4) = make_uint2(bfpack(h0, h1), bfpack(h2, h3));
    *reinterpret_cast<uint2*>(lo + (size_t)i * 4) = make_uint2(bfpack(l0, l1), bfpack(l2, l3));
}

// ============ weight prep, all 3 layers in one launch ============
__global__ void prep_w_kernel(const float* __restrict__ Wrel1, const float* __restrict__ Wroot1,
                              const float* __restrict__ Wrel2, const float* __restrict__ Wroot2,
                              const float* __restrict__ Wrel3, const float* __restrict__ Wroot3,
                              __nv_bfloat16* __restrict__ hi, __nv_bfloat16* __restrict__ lo) {
    int i = blockIdx.x * blockDim.x + threadIdx.x;
    if (i >= 3 * 256 * 128) return;
    int l = i >> 15;
    int j = i & 32767;
    int k = j >> 7, n = j & 127;
    const float* Wrel  = (l == 0) ? Wrel1  : (l == 1) ? Wrel2  : Wrel3;
    const float* Wroot = (l == 0) ? Wroot1 : (l == 1) ? Wroot2 : Wroot3;
    float v = (k < 128) ? Wrel[k * 128 + n] : Wroot[(k - 128) * 128 + n];
    __nv_bfloat16 h, lw;
    split_bf(v, h, lw);
    hi[i] = h; lo[i] = lw;
}

// ============ aggregation: one warp per node; reads hi/lo planes; writes hi/lo ============
__global__ void gather_agg_kernel(const __nv_bfloat16* __restrict__ inhi,
                                  const __nv_bfloat16* __restrict__ inlo,
                                  const int* __restrict__ rowptr,
                                  const uint2* __restrict__ csr,
                                  __nv_bfloat16* __restrict__ agghi,
                                  __nv_bfloat16* __restrict__ agglo) {
    unsigned gt = blockIdx.x * blockDim.x + threadIdx.x;
    unsigned node = gt >> 5;
    int lane = threadIdx.x & 31;
    if (node >= NN) return;
    int s0 = __ldg(rowptr + node);
    int s1 = __ldg(rowptr + node + 1);
    float4 acc = make_float4(0.f, 0.f, 0.f, 0.f);
    int e = s0;
    for (; e + 1 < s1; e += 2) {
        uint2 e0 = __ldg(csr + e);
        uint2 e1 = __ldg(csr + e + 1);
        size_t o0 = (size_t)e0.x * DH + lane * 4;
        size_t o1 = (size_t)e1.x * DH + lane * 4;
        uint2 h0 = *reinterpret_cast<const uint2*>(inhi + o0);
        uint2 l0 = *reinterpret_cast<const uint2*>(inlo + o0);
        uint2 h1 = *reinterpret_cast<const uint2*>(inhi + o1);
        uint2 l1 = *reinterpret_cast<const uint2*>(inlo + o1);
        float w0 = __uint_as_float(e0.y), w1 = __uint_as_float(e1.y);
        float2 a, b;
        a = bf2f2(h0.x); b = bf2f2(l0.x);
        acc.x = fmaf(w0, a.x + b.x, acc.x); acc.y = fmaf(w0, a.y + b.y, acc.y);
        a = bf2f2(h0.y); b = bf2f2(l0.y);
        acc.z = fmaf(w0, a.x + b.x, acc.z); acc.w = fmaf(w0, a.y + b.y, acc.w);
        a = bf2f2(h1.x); b = bf2f2(l1.x);
        acc.x = fmaf(w1, a.x + b.x, acc.x); acc.y = fmaf(w1, a.y + b.y, acc.y);
        a = bf2f2(h1.y); b = bf2f2(l1.y);
        acc.z = fmaf(w1, a.x + b.x, acc.z); acc.w = fmaf(w1, a.y + b.y, acc.w);
    }
    if (e < s1) {
        uint2 e0 = __ldg(csr + e);
        size_t o0 = (size_t)e0.x * DH + lane * 4;
        uint2 h0 = *reinterpret_cast<const uint2*>(inhi + o0);
        uint2 l0 = *reinterpret_cast<const uint2*>(inlo + o0);
        float w0 = __uint_as_float(e0.y);
        float2 a, b;
        a = bf2f2(h0.x); b = bf2f2(l0.x);
        acc.x = fmaf(w0, a.x + b.x, acc.x); acc.y = fmaf(w0, a.y + b.y, acc.y);
        a = bf2f2(h0.y); b = bf2f2(l0.y);
        acc.z = fmaf(w0, a.x + b.x, acc.z); acc.w = fmaf(w0, a.y + b.y, acc.w);
    }
    float di = (s1 > s0) ? 1.0f / (float)(s1 - s0) : 0.f;
    acc.x *= di; acc.y *= di; acc.z *= di; acc.w *= di;

    __nv_bfloat16 h0, l0, h1, l1, h2, l2, h3, l3;
    split_bf(acc.x, h0, l0); split_bf(acc.y, h1, l1);
    split_bf(acc.z, h2, l2); split_bf(acc.w, h3, l3);
    size_t off = (size_t)node * DH + lane * 4;
    *reinterpret_cast<uint2*>(agghi + off) = make_uint2(bfpack(h0, h1), bfpack(h2, h3));
    *reinterpret_cast<uint2*>(agglo + off) = make_uint2(bfpack(l0, l1), bfpack(l2, l3));
}

// ============ persistent wmma GEMM: relu([agg|x]@[Wrel;Wroot] + b) ============
// 148 CTAs x 512 threads (16 warps, 4x4, 32x32 warp tiles). B hi/lo smem-resident.
// A chunks staged by cp.async (bf16 hi/lo direct), 3-stage ring, 2-deep prefetch.
// Fragments scoped tightly to stay under the 128-reg/thread cap (512 thr, 1 CTA/SM).
#define BSTR 136
#define ASTR 40
#define OFF_BH 0u
#define OFF_BL 69632u
#define OFF_BB 139264u                       // bias B chunk: 16 x BSTR
#define OFF_AB 143616u                       // bias A chunk: 128 x ASTR (cols 0,1 = 1)
#define OFF_A  153856u                       // 3 stages x (AH 10240 + AL 10240)
#define GEMM_SMEM (153856 + 3 * 20480)       // 215296

__global__ void __launch_bounds__(512, 1) gemm_persist_kernel(
    const __nv_bfloat16* __restrict__ agghi, const __nv_bfloat16* __restrict__ agglo,
    const __nv_bfloat16* __restrict__ xhi,   const __nv_bfloat16* __restrict__ xlo,
    const __nv_bfloat16* __restrict__ whi,   const __nv_bfloat16* __restrict__ wlo,
    const float* __restrict__ bias,
    __nv_bfloat16* __restrict__ outhi, __nv_bfloat16* __restrict__ outlo,  // intermediate
    float* __restrict__ foutv, float* __restrict__ tail, int final_layer)  // final
{
    extern __shared__ char smem[];
    __nv_bfloat16* BH = reinterpret_cast<__nv_bfloat16*>(smem + OFF_BH);
    __nv_bfloat16* BL = reinterpret_cast<__nv_bfloat16*>(smem + OFF_BL);
    __nv_bfloat16* BB = reinterpret_cast<__nv_bfloat16*>(smem + OFF_BB);
    __nv_bfloat16* AB = reinterpret_cast<__nv_bfloat16*>(smem + OFF_AB);
    uint32_t smemA;
    {
        uint32_t a;
        asm("{ .reg .u64 t; cvta.to.shared.u64 t, %1; cvt.u32.u64 %0, t; }" : "=r"(a) : "l"(smem + OFF_A));
        smemA = a;
    }

    const int tid = threadIdx.x;
    const int wid = tid >> 5;
    const int wm = wid >> 2;      // 0..3 -> rows 32*wm
    const int wn = wid & 3;       // 0..3 -> cols 32*wn
    const int r = tid >> 2;       // 0..127  (A staging row)
    const int quarter = tid & 3;  // 8 bf16 = 16B each

    // one-time staging: B hi/lo, bias chunks
    #pragma unroll
    for (int j = 0; j < 8; j++) {
        int f = tid + j * 512;
        int rr = f >> 4, c8 = f & 15;
        uint4 vh = *reinterpret_cast<const uint4*>(whi + (size_t)rr * 128 + c8 * 8);
        uint4 vl = *reinterpret_cast<const uint4*>(wlo + (size_t)rr * 128 + c8 * 8);
        *reinterpret_cast<uint4*>(BH + rr * BSTR + c8 * 8) = vh;
        *reinterpret_cast<uint4*>(BL + rr * BSTR + c8 * 8) = vl;
    }
    for (int i = tid; i < (16 * BSTR + 128 * ASTR) / 2; i += 512)
        reinterpret_cast<uint32_t*>(BB)[i] = 0;
    __syncthreads();
    if (tid < 128) {
        __nv_bfloat16 h, l;
        split_bf(bias[tid], h, l);
        BB[0 * BSTR + tid] = h;
        BB[1 * BSTR + tid] = l;
        AB[tid * ASTR + 0] = __float2bfloat16_rn(1.0f);
        AB[tid * ASTR + 1] = __float2bfloat16_rn(1.0f);
    }
    __syncthreads();

    for (int tile = blockIdx.x; tile < NTILES; tile += 148) {
        const int row0 = tile * 128;
        const int grow = row0 + r;
        const int sz = (grow < NN) ? 16 : 0;

        auto issue = [&](int c) {
            const __nv_bfloat16* ph = (c < 4) ? agghi : xhi;
            const __nv_bfloat16* pl = (c < 4) ? agglo : xlo;
            const int k0 = (c & 3) * 32;
            const __nv_bfloat16* sh = ph + (size_t)grow * DH + k0 + quarter * 8;
            const __nv_bfloat16* sl = pl + (size_t)grow * DH + k0 + quarter * 8;
            uint32_t dh = smemA + (uint32_t)(c % 3) * 20480u + (uint32_t)(r * ASTR + quarter * 8) * 2u;
            uint32_t dl = dh + 10240u;
            asm volatile("cp.async.cg.shared.global [%0], [%1], 16, %2;" :: "r"(dh), "l"(sh), "r"(sz));
            asm volatile("cp.async.cg.shared.global [%0], [%1], 16, %2;" :: "r"(dl), "l"(sl), "r"(sz));
            asm volatile("cp.async.commit_group;");
        };

        wmma::fragment<wmma::accumulator, 16, 16, 16, float> acc[2][2];
        #pragma unroll
        for (int i = 0; i < 2; i++)
            #pragma unroll
            for (int j = 0; j < 2; j++) wmma::fill_fragment(acc[i][j], 0.f);

        // bias rank-1 chunk (scoped fragments)
        {
            wmma::fragment<wmma::matrix_b, 16, 16, 16, __nv_bfloat16, wmma::row_major> fb[2];
            #pragma unroll
            for (int j = 0; j < 2; j++)
                wmma::load_matrix_sync(fb[j], BB + 32 * wn + 16 * j, BSTR);
            #pragma unroll
            for (int i = 0; i < 2; i++) {
                wmma::fragment<wmma::matrix_a, 16, 16, 16, __nv_bfloat16, wmma::row_major> fa;
                wmma::load_matrix_sync(fa, AB + (32 * wm + 16 * i) * ASTR, ASTR);
                #pragma unroll
                for (int j = 0; j < 2; j++)
                    wmma::mma_sync(acc[i][j], fa, fb[j], acc[i][j]);
            }
        }

        issue(0);
        issue(1);

        #pragma unroll 1
        for (int c = 0; c < 8; c++) {
            if (c < 6) {
                issue(c + 2);
                asm volatile("cp.async.wait_group 2;");
            } else if (c == 6) {
                asm volatile("cp.async.wait_group 1;");
            } else {
                asm volatile("cp.async.wait_group 0;");
            }
            __syncthreads();
            const __nv_bfloat16* AHc = reinterpret_cast<const __nv_bfloat16*>(smem + OFF_A + (c % 3) * 20480);
            const __nv_bfloat16* ALc = AHc + 5120;   // 10240 bytes
            #pragma unroll
            for (int kk = 0; kk < 2; kk++) {
                const int krow = c * 32 + kk * 16;
                wmma::fragment<wmma::matrix_b, 16, 16, 16, __nv_bfloat16, wmma::row_major> fbh[2], fbl[2];
                #pragma unroll
                for (int j = 0; j < 2; j++) {
                    wmma::load_matrix_sync(fbh[j], BH + krow * BSTR + 32 * wn + 16 * j, BSTR);
                    wmma::load_matrix_sync(fbl[j], BL + krow * BSTR + 32 * wn + 16 * j, BSTR);
                }
                #pragma unroll
                for (int i = 0; i < 2; i++) {
                    wmma::fragment<wmma::matrix_a, 16, 16, 16, __nv_bfloat16, wmma::row_major> fah, fal;
                    wmma::load_matrix_sync(fah, AHc + (32 * wm + 16 * i) * ASTR + kk * 16, ASTR);
                    wmma::load_matrix_sync(fal, ALc + (32 * wm + 16 * i) * ASTR + kk * 16, ASTR);
                    #pragma unroll
                    for (int j = 0; j < 2; j++) {
                        wmma::mma_sync(acc[i][j], fah, fbh[j], acc[i][j]);
                        wmma::mma_sync(acc[i][j], fah, fbl[j], acc[i][j]);
                        wmma::mma_sync(acc[i][j], fal, fbh[j], acc[i][j]);
                    }
                }
            }
        }

        // relu on fragments
        #pragma unroll
        for (int i = 0; i < 2; i++)
            #pragma unroll
            for (int j = 0; j < 2; j++)
                #pragma unroll
                for (int e = 0; e < acc[i][j].num_elements; e++)
                    acc[i][j].x[e] = fmaxf(acc[i][j].x[e], 0.f);

        if (!final_layer) {
            // write hi/lo planes via smem roundtrip, 64 rows per pass (scratch = A region)
            float* scr = reinterpret_cast<float*>(smem + OFF_A);   // 64 x 132 f32 = 33792 B
            #pragma unroll 1
            for (int hh = 0; hh < 2; hh++) {
                __syncthreads();
                if ((wm >> 1) == hh) {
                    int lr = 32 * (wm & 1);
                    #pragma unroll
                    for (int i = 0; i < 2; i++)
                        #pragma unroll
                        for (int j = 0; j < 2; j++)
                            wmma::store_matrix_sync(scr + (lr + 16 * i) * 132 + 32 * wn + 16 * j,
                                                    acc[i][j], 132, wmma::mem_row_major);
                }
                __syncthreads();
                int r6 = tid >> 3;      // 0..63
                int part = tid & 7;     // 16 elems
                int gr = row0 + hh * 64 + r6;
                if (gr < NN) {
                    const float* srow = scr + r6 * 132 + part * 16;
                    uint32_t hp[8], lp[8];
                    #pragma unroll
                    for (int q = 0; q < 8; q++) {
                        __nv_bfloat16 h0, l0, h1, l1;
                        split_bf(srow[2 * q], h0, l0);
                        split_bf(srow[2 * q + 1], h1, l1);
                        hp[q] = bfpack(h0, h1);
                        lp[q] = bfpack(l0, l1);
                    }
                    size_t off = (size_t)gr * DH + part * 16;
                    *reinterpret_cast<uint4*>(outhi + off)     = *reinterpret_cast<uint4*>(hp);
                    *reinterpret_cast<uint4*>(outhi + off + 8) = *reinterpret_cast<uint4*>(hp + 4);
                    *reinterpret_cast<uint4*>(outlo + off)     = *reinterpret_cast<uint4*>(lp);
                    *reinterpret_cast<uint4*>(outlo + off + 8) = *reinterpret_cast<uint4*>(lp + 4);
                }
            }
            __syncthreads();   // scratch becomes A ring again next tile
        } else {
            if (row0 + 128 <= NN) {
                #pragma unroll
                for (int i = 0; i < 2; i++)
                    #pragma unroll
                    for (int j = 0; j < 2; j++)
                        wmma::store_matrix_sync(foutv + (size_t)(row0 + 32 * wm + 16 * i) * DH + 32 * wn + 16 * j,
                                                acc[i][j], DH, wmma::mem_row_major);
            } else {
                #pragma unroll
                for (int i = 0; i < 2; i++)
                    #pragma unroll
                    for (int j = 0; j < 2; j++)
                        wmma::store_matrix_sync(tail + (size_t)(32 * wm + 16 * i) * DH + 32 * wn + 16 * j,
                                                acc[i][j], DH, wmma::mem_row_major);
                __syncthreads();
                if (grow < NN) {
                    const float* srow = tail + (size_t)r * DH + quarter * 32;
                    float* drow = foutv + (size_t)grow * DH + quarter * 32;
                    #pragma unroll
                    for (int q = 0; q < 8; q++)
                        *reinterpret_cast<float4*>(drow + q * 4) =
                            *reinterpret_cast<const float4*>(srow + q * 4);
                }
            }
            __syncthreads();
        }
    }
}

// ============ host ============
extern "C" void kernel_launch(void* const* d_in, const int* in_sizes, int n_in,
                              void* d_out, int out_size) {
    const float* x      = (const float*)d_in[0];
    const int*   ei     = (const int*)d_in[1];
    const float* ea     = (const float*)d_in[2];
    const float* Wrel1  = (const float*)d_in[3];
    const float* b1     = (const float*)d_in[4];
    const float* Wroot1 = (const float*)d_in[5];
    const float* Wrel2  = (const float*)d_in[6];
    const float* b2     = (const float*)d_in[7];
    const float* Wroot2 = (const float*)d_in[8];
    const float* Wrel3  = (const float*)d_in[9];
    const float* b3     = (const float*)d_in[10];
    const float* Wroot3 = (const float*)d_in[11];
    float* out = (float*)d_out;

    const int* src = ei;
    const int* dst = ei + NE;

    int *deg, *rowptr, *cursor;
    uint2 *csr;
    float *tail;
    __nv_bfloat16 *agghi, *agglo, *xhi, *xlo, *h1hi, *h1lo, *h2hi, *h2lo, *whi, *wlo;
    cudaGetSymbolAddress((void**)&deg,    g_deg);
    cudaGetSymbolAddress((void**)&rowptr, g_rowptr);
    cudaGetSymbolAddress((void**)&cursor, g_cursor);
    cudaGetSymbolAddress((void**)&csr,    g_csr);
    cudaGetSymbolAddress((void**)&agghi,  g_agghi);
    cudaGetSymbolAddress((void**)&agglo,  g_agglo);
    cudaGetSymbolAddress((void**)&xhi,    g_xhi);
    cudaGetSymbolAddress((void**)&xlo,    g_xlo);
    cudaGetSymbolAddress((void**)&h1hi,   g_h1hi);
    cudaGetSymbolAddress((void**)&h1lo,   g_h1lo);
    cudaGetSymbolAddress((void**)&h2hi,   g_h2hi);
    cudaGetSymbolAddress((void**)&h2lo,   g_h2lo);
    cudaGetSymbolAddress((void**)&tail,   g_tail);
    cudaGetSymbolAddress((void**)&whi,    g_whi);
    cudaGetSymbolAddress((void**)&wlo,    g_wlo);

    cudaFuncSetAttribute(gemm_persist_kernel,
                         cudaFuncAttributeMaxDynamicSharedMemorySize, GEMM_SMEM);

    // CSR build + splits (once)
    cudaMemsetAsync(deg, 0, NN * sizeof(int));
    deg_count_kernel<<<(NE + 255) / 256, 256>>>(dst, deg);
    scan_kernel<<<1, 1024>>>(deg, rowptr, cursor);
    fill_csr_kernel<<<(NE + 255) / 256, 256>>>(src, dst, ea, cursor, csr);
    split_x_kernel<<<(NN * DH / 4 + 255) / 256, 256>>>(x, xhi, xlo);
    prep_w_kernel<<<(3 * 256 * 128 + 255) / 256, 256>>>(Wrel1, Wroot1, Wrel2, Wroot2, Wrel3, Wroot3, whi, wlo);

    const __nv_bfloat16* inhi[3] = {xhi, h1hi, h2hi};
    const __nv_bfloat16* inlo[3] = {xlo, h1lo, h2lo};
    __nv_bfloat16* ohi[3] = {h1hi, h2hi, nullptr};
    __nv_bfloat16* olo[3] = {h1lo, h2lo, nullptr};
    const float* bv[3] = {b1, b2, b3};

    int gather_blocks = (NN * 32 + 255) / 256;
    for (int l = 0; l < 3; l++) {
        gather_agg_kernel<<<gather_blocks, 256>>>(inhi[l], inlo[l], rowptr, csr, agghi, agglo);
        gemm_persist_kernel<<<148, 512, GEMM_SMEM>>>(
            agghi, agglo, inhi[l], inlo[l],
            whi + l * 32768, wlo + l * 32768, bv[l],
            ohi[l], olo[l], out, tail, l == 2 ? 1 : 0);
    }
}

// round 10
// speedup vs baseline: 1.0198x; 1.0198x over previous
#include <cuda_runtime.h>
#include <cuda_bf16.h>
#include <mma.h>
#include <stdint.h>

using namespace nvcuda;

#define NN 100000
#define NE 1600000
#define DH 128
#define NTILES 782   // ceil(NN/128)

// ---- scratch (device globals; no allocation allowed) ----
__device__ int   g_deg[NN];
__device__ int   g_rowptr[NN + 1];
__device__ int   g_cursor[NN];
__device__ uint2 g_csr[NE];                      // (src, w-bits) packed
__device__ __nv_bfloat16 g_agghi[NN * DH];
__device__ __nv_bfloat16 g_agglo[NN * DH];
__device__ __nv_bfloat16 g_xhi[NN * DH];
__device__ __nv_bfloat16 g_xlo[NN * DH];
__device__ __nv_bfloat16 g_h1hi[NN * DH];
__device__ __nv_bfloat16 g_h1lo[NN * DH];
__device__ __nv_bfloat16 g_h2hi[NN * DH];
__device__ __nv_bfloat16 g_h2lo[NN * DH];
__device__ float g_tail[128 * DH];
__device__ __nv_bfloat16 g_whi[3 * 256 * 128];   // [layer][k][n] : k<128 Wrel, k>=128 Wroot
__device__ __nv_bfloat16 g_wlo[3 * 256 * 128];

// ============ small helpers ============
__device__ __forceinline__ uint32_t bfpack(__nv_bfloat16 a, __nv_bfloat16 b) {
    return (uint32_t)__bfloat16_as_ushort(a) | ((uint32_t)__bfloat16_as_ushort(b) << 16);
}
__device__ __forceinline__ void split_bf(float v, __nv_bfloat16& h, __nv_bfloat16& l) {
    h = __float2bfloat16_rn(v);
    l = __float2bfloat16_rn(v - __bfloat162float(h));
}
__device__ __forceinline__ float2 bf2f2(uint32_t u) {
    __nv_bfloat162 b = *reinterpret_cast<__nv_bfloat162*>(&u);
    return __bfloat1622float2(b);
}

// ============ fused prep: zero deg + split x + prep weights (launch #1) ============
#define XQUADS (NN * DH / 4)                 // 3,200,000
#define WELEMS (3 * 256 * 128)               // 98,304
__global__ void prep_all_kernel(const float* __restrict__ x,
                                const float* __restrict__ Wrel1, const float* __restrict__ Wroot1,
                                const float* __restrict__ Wrel2, const float* __restrict__ Wroot2,
                                const float* __restrict__ Wrel3, const float* __restrict__ Wroot3,
                                __nv_bfloat16* __restrict__ xhi, __nv_bfloat16* __restrict__ xlo,
                                __nv_bfloat16* __restrict__ whi, __nv_bfloat16* __restrict__ wlo,
                                int* __restrict__ deg) {
    int i = blockIdx.x * blockDim.x + threadIdx.x;
    if (i < XQUADS) {
        float4 v = *reinterpret_cast<const float4*>(x + (size_t)i * 4);
        __nv_bfloat16 h0, l0, h1, l1, h2, l2, h3, l3;
        split_bf(v.x, h0, l0); split_bf(v.y, h1, l1);
        split_bf(v.z, h2, l2); split_bf(v.w, h3, l3);
        *reinterpret_cast<uint2*>(xhi + (size_t)i * 4) = make_uint2(bfpack(h0, h1), bfpack(h2, h3));
        *reinterpret_cast<uint2*>(xlo + (size_t)i * 4) = make_uint2(bfpack(l0, l1), bfpack(l2, l3));
    } else if (i < XQUADS + NN) {
        deg[i - XQUADS] = 0;
    } else if (i < XQUADS + NN + WELEMS) {
        int w = i - (XQUADS + NN);
        int l = w >> 15;
        int j = w & 32767;
        int k = j >> 7, n = j & 127;
        const float* Wrel  = (l == 0) ? Wrel1  : (l == 1) ? Wrel2  : Wrel3;
        const float* Wroot = (l == 0) ? Wroot1 : (l == 1) ? Wroot2 : Wroot3;
        float v = (k < 128) ? Wrel[k * 128 + n] : Wroot[(k - 128) * 128 + n];
        __nv_bfloat16 h, lw;
        split_bf(v, h, lw);
        whi[w] = h; wlo[w] = lw;
    }
}

// ============ CSR build ============
__global__ void deg_count_kernel(const int* __restrict__ dst, int* __restrict__ deg) {
    int i = blockIdx.x * blockDim.x + threadIdx.x;
    if (i < NE) atomicAdd(&deg[dst[i]], 1);
}

__global__ void scan_kernel(const int* __restrict__ deg,
                            int* __restrict__ rowptr, int* __restrict__ cursor) {
    __shared__ int wsum[32];
    __shared__ int carry;
    const int tid = threadIdx.x, lane = tid & 31, warp = tid >> 5;
    if (tid == 0) carry = 0;
    __syncthreads();
    for (int base = 0; base < NN; base += 1024) {
        int i = base + tid;
        int v = (i < NN) ? deg[i] : 0;
        int s = v;
        #pragma unroll
        for (int off = 1; off < 32; off <<= 1) {
            int t = __shfl_up_sync(0xFFFFFFFF, s, off);
            if (lane >= off) s += t;
        }
        if (lane == 31) wsum[warp] = s;
        __syncthreads();
        if (warp == 0) {
            int w = wsum[lane];
            #pragma unroll
            for (int off = 1; off < 32; off <<= 1) {
                int t = __shfl_up_sync(0xFFFFFFFF, w, off);
                if (lane >= off) w += t;
            }
            wsum[lane] = w;
        }
        __syncthreads();
        int excl = s - v + (warp > 0 ? wsum[warp - 1] : 0) + carry;
        if (i < NN) { rowptr[i] = excl; cursor[i] = excl; }
        __syncthreads();
        if (tid == 0) carry += wsum[31];
        __syncthreads();
    }
    if (threadIdx.x == 0) rowptr[NN] = carry;
}

__global__ void fill_csr_kernel(const int* __restrict__ src, const int* __restrict__ dst,
                                const float* __restrict__ w, int* __restrict__ cursor,
                                uint2* __restrict__ csr) {
    int e = blockIdx.x * blockDim.x + threadIdx.x;
    if (e < NE) {
        int d = dst[e];
        int p = atomicAdd(&cursor[d], 1);
        csr[p] = make_uint2((unsigned)src[e], __float_as_uint(w[e]));
    }
}

// ============ aggregation: one warp per node; reads hi/lo planes; writes hi/lo ============
__global__ void gather_agg_kernel(const __nv_bfloat16* __restrict__ inhi,
                                  const __nv_bfloat16* __restrict__ inlo,
                                  const int* __restrict__ rowptr,
                                  const uint2* __restrict__ csr,
                                  __nv_bfloat16* __restrict__ agghi,
                                  __nv_bfloat16* __restrict__ agglo) {
    unsigned gt = blockIdx.x * blockDim.x + threadIdx.x;
    unsigned node = gt >> 5;
    int lane = threadIdx.x & 31;
    if (node >= NN) return;
    int s0 = __ldg(rowptr + node);
    int s1 = __ldg(rowptr + node + 1);
    float4 acc = make_float4(0.f, 0.f, 0.f, 0.f);
    int e = s0;
    for (; e + 1 < s1; e += 2) {
        uint2 e0 = __ldg(csr + e);
        uint2 e1 = __ldg(csr + e + 1);
        size_t o0 = (size_t)e0.x * DH + lane * 4;
        size_t o1 = (size_t)e1.x * DH + lane * 4;
        uint2 h0 = *reinterpret_cast<const uint2*>(inhi + o0);
        uint2 l0 = *reinterpret_cast<const uint2*>(inlo + o0);
        uint2 h1 = *reinterpret_cast<const uint2*>(inhi + o1);
        uint2 l1 = *reinterpret_cast<const uint2*>(inlo + o1);
        float w0 = __uint_as_float(e0.y), w1 = __uint_as_float(e1.y);
        float2 a, b;
        a = bf2f2(h0.x); b = bf2f2(l0.x);
        acc.x = fmaf(w0, a.x + b.x, acc.x); acc.y = fmaf(w0, a.y + b.y, acc.y);
        a = bf2f2(h0.y); b = bf2f2(l0.y);
        acc.z = fmaf(w0, a.x + b.x, acc.z); acc.w = fmaf(w0, a.y + b.y, acc.w);
        a = bf2f2(h1.x); b = bf2f2(l1.x);
        acc.x = fmaf(w1, a.x + b.x, acc.x); acc.y = fmaf(w1, a.y + b.y, acc.y);
        a = bf2f2(h1.y); b = bf2f2(l1.y);
        acc.z = fmaf(w1, a.x + b.x, acc.z); acc.w = fmaf(w1, a.y + b.y, acc.w);
    }
    if (e < s1) {
        uint2 e0 = __ldg(csr + e);
        size_t o0 = (size_t)e0.x * DH + lane * 4;
        uint2 h0 = *reinterpret_cast<const uint2*>(inhi + o0);
        uint2 l0 = *reinterpret_cast<const uint2*>(inlo + o0);
        float w0 = __uint_as_float(e0.y);
        float2 a, b;
        a = bf2f2(h0.x); b = bf2f2(l0.x);
        acc.x = fmaf(w0, a.x + b.x, acc.x); acc.y = fmaf(w0, a.y + b.y, acc.y);
        a = bf2f2(h0.y); b = bf2f2(l0.y);
        acc.z = fmaf(w0, a.x + b.x, acc.z); acc.w = fmaf(w0, a.y + b.y, acc.w);
    }
    float di = (s1 > s0) ? 1.0f / (float)(s1 - s0) : 0.f;
    acc.x *= di; acc.y *= di; acc.z *= di; acc.w *= di;

    __nv_bfloat16 h0, l0, h1, l1, h2, l2, h3, l3;
    split_bf(acc.x, h0, l0); split_bf(acc.y, h1, l1);
    split_bf(acc.z, h2, l2); split_bf(acc.w, h3, l3);
    size_t off = (size_t)node * DH + lane * 4;
    *reinterpret_cast<uint2*>(agghi + off) = make_uint2(bfpack(h0, h1), bfpack(h2, h3));
    *reinterpret_cast<uint2*>(agglo + off) = make_uint2(bfpack(l0, l1), bfpack(l2, l3));
}

// ============ persistent wmma GEMM: relu([agg|x]@[Wrel;Wroot] + b) ============
// (round-8 structure — best measured)
#define BSTR 136
#define ASTR 40
#define OFF_BH 0u
#define OFF_BL 69632u
#define OFF_BB 139264u                       // bias B chunk: 16 x BSTR
#define OFF_AB 143616u                       // bias A chunk: 128 x ASTR (cols 0,1 = 1)
#define OFF_A  153856u                       // 3 stages x (AH 10240 + AL 10240)
#define GEMM_SMEM (153856 + 3 * 20480)       // 215296

__global__ void __launch_bounds__(512, 1) gemm_persist_kernel(
    const __nv_bfloat16* __restrict__ agghi, const __nv_bfloat16* __restrict__ agglo,
    const __nv_bfloat16* __restrict__ xhi,   const __nv_bfloat16* __restrict__ xlo,
    const __nv_bfloat16* __restrict__ whi,   const __nv_bfloat16* __restrict__ wlo,
    const float* __restrict__ bias,
    __nv_bfloat16* __restrict__ outhi, __nv_bfloat16* __restrict__ outlo,  // intermediate
    float* __restrict__ foutv, float* __restrict__ tail, int final_layer)  // final
{
    extern __shared__ char smem[];
    __nv_bfloat16* BH = reinterpret_cast<__nv_bfloat16*>(smem + OFF_BH);
    __nv_bfloat16* BL = reinterpret_cast<__nv_bfloat16*>(smem + OFF_BL);
    __nv_bfloat16* BB = reinterpret_cast<__nv_bfloat16*>(smem + OFF_BB);
    __nv_bfloat16* AB = reinterpret_cast<__nv_bfloat16*>(smem + OFF_AB);
    uint32_t smemA;
    {
        uint32_t a;
        asm("{ .reg .u64 t; cvta.to.shared.u64 t, %1; cvt.u32.u64 %0, t; }" : "=r"(a) : "l"(smem + OFF_A));
        smemA = a;
    }

    const int tid = threadIdx.x;
    const int wid = tid >> 5;
    const int wm = wid >> 2;      // 0..3 -> rows 32*wm
    const int wn = wid & 3;       // 0..3 -> cols 32*wn
    const int r = tid >> 2;       // 0..127  (A staging row)
    const int quarter = tid & 3;  // 8 bf16 = 16B each

    // one-time staging: B hi/lo, bias chunks
    #pragma unroll
    for (int j = 0; j < 8; j++) {
        int f = tid + j * 512;
        int rr = f >> 4, c8 = f & 15;
        uint4 vh = *reinterpret_cast<const uint4*>(whi + (size_t)rr * 128 + c8 * 8);
        uint4 vl = *reinterpret_cast<const uint4*>(wlo + (size_t)rr * 128 + c8 * 8);
        *reinterpret_cast<uint4*>(BH + rr * BSTR + c8 * 8) = vh;
        *reinterpret_cast<uint4*>(BL + rr * BSTR + c8 * 8) = vl;
    }
    for (int i = tid; i < (16 * BSTR + 128 * ASTR) / 2; i += 512)
        reinterpret_cast<uint32_t*>(BB)[i] = 0;
    __syncthreads();
    if (tid < 128) {
        __nv_bfloat16 h, l;
        split_bf(bias[tid], h, l);
        BB[0 * BSTR + tid] = h;
        BB[1 * BSTR + tid] = l;
        AB[tid * ASTR + 0] = __float2bfloat16_rn(1.0f);
        AB[tid * ASTR + 1] = __float2bfloat16_rn(1.0f);
    }
    __syncthreads();

    for (int tile = blockIdx.x; tile < NTILES; tile += 148) {
        const int row0 = tile * 128;
        const int grow = row0 + r;
        const int sz = (grow < NN) ? 16 : 0;

        auto issue = [&](int c) {
            const __nv_bfloat16* ph = (c < 4) ? agghi : xhi;
            const __nv_bfloat16* pl = (c < 4) ? agglo : xlo;
            const int k0 = (c & 3) * 32;
            const __nv_bfloat16* sh = ph + (size_t)grow * DH + k0 + quarter * 8;
            const __nv_bfloat16* sl = pl + (size_t)grow * DH + k0 + quarter * 8;
            uint32_t dh = smemA + (uint32_t)(c % 3) * 20480u + (uint32_t)(r * ASTR + quarter * 8) * 2u;
            uint32_t dl = dh + 10240u;
            asm volatile("cp.async.cg.shared.global [%0], [%1], 16, %2;" :: "r"(dh), "l"(sh), "r"(sz));
            asm volatile("cp.async.cg.shared.global [%0], [%1], 16, %2;" :: "r"(dl), "l"(sl), "r"(sz));
            asm volatile("cp.async.commit_group;");
        };

        wmma::fragment<wmma::accumulator, 16, 16, 16, float> acc[2][2];
        #pragma unroll
        for (int i = 0; i < 2; i++)
            #pragma unroll
            for (int j = 0; j < 2; j++) wmma::fill_fragment(acc[i][j], 0.f);

        // bias rank-1 chunk
        {
            wmma::fragment<wmma::matrix_a, 16, 16, 16, __nv_bfloat16, wmma::row_major> fa[2];
            wmma::fragment<wmma::matrix_b, 16, 16, 16, __nv_bfloat16, wmma::row_major> fb[2];
            #pragma unroll
            for (int i = 0; i < 2; i++)
                wmma::load_matrix_sync(fa[i], AB + (32 * wm + 16 * i) * ASTR, ASTR);
            #pragma unroll
            for (int j = 0; j < 2; j++)
                wmma::load_matrix_sync(fb[j], BB + 32 * wn + 16 * j, BSTR);
            #pragma unroll
            for (int i = 0; i < 2; i++)
                #pragma unroll
                for (int j = 0; j < 2; j++)
                    wmma::mma_sync(acc[i][j], fa[i], fb[j], acc[i][j]);
        }

        issue(0);

        #pragma unroll 1
        for (int c = 0; c < 8; c++) {
            if (c < 7) {
                issue(c + 1);
                asm volatile("cp.async.wait_group 1;");
            } else {
                asm volatile("cp.async.wait_group 0;");
            }
            __syncthreads();
            const __nv_bfloat16* AHc = reinterpret_cast<const __nv_bfloat16*>(smem + OFF_A + (c % 3) * 20480);
            const __nv_bfloat16* ALc = AHc + 5120;   // 10240 bytes
            #pragma unroll
            for (int kk = 0; kk < 2; kk++) {
                wmma::fragment<wmma::matrix_a, 16, 16, 16, __nv_bfloat16, wmma::row_major> fah[2], fal[2];
                wmma::fragment<wmma::matrix_b, 16, 16, 16, __nv_bfloat16, wmma::row_major> fbh[2], fbl[2];
                #pragma unroll
                for (int i = 0; i < 2; i++) {
                    wmma::load_matrix_sync(fah[i], AHc + (32 * wm + 16 * i) * ASTR + kk * 16, ASTR);
                    wmma::load_matrix_sync(fal[i], ALc + (32 * wm + 16 * i) * ASTR + kk * 16, ASTR);
                }
                const int krow = c * 32 + kk * 16;
                #pragma unroll
                for (int j = 0; j < 2; j++) {
                    wmma::load_matrix_sync(fbh[j], BH + krow * BSTR + 32 * wn + 16 * j, BSTR);
                    wmma::load_matrix_sync(fbl[j], BL + krow * BSTR + 32 * wn + 16 * j, BSTR);
                }
                #pragma unroll
                for (int i = 0; i < 2; i++)
                    #pragma unroll
                    for (int j = 0; j < 2; j++) {
                        wmma::mma_sync(acc[i][j], fah[i], fbh[j], acc[i][j]);
                        wmma::mma_sync(acc[i][j], fah[i], fbl[j], acc[i][j]);
                        wmma::mma_sync(acc[i][j], fal[i], fbh[j], acc[i][j]);
                    }
            }
        }

        // relu on fragments
        #pragma unroll
        for (int i = 0; i < 2; i++)
            #pragma unroll
            for (int j = 0; j < 2; j++)
                #pragma unroll
                for (int e = 0; e < acc[i][j].num_elements; e++)
                    acc[i][j].x[e] = fmaxf(acc[i][j].x[e], 0.f);

        if (!final_layer) {
            float* scr = reinterpret_cast<float*>(smem + OFF_A);   // 64 x 132 f32
            #pragma unroll 1
            for (int hh = 0; hh < 2; hh++) {
                __syncthreads();
                if ((wm >> 1) == hh) {
                    int lr = 32 * (wm & 1);
                    #pragma unroll
                    for (int i = 0; i < 2; i++)
                        #pragma unroll
                        for (int j = 0; j < 2; j++)
                            wmma::store_matrix_sync(scr + (lr + 16 * i) * 132 + 32 * wn + 16 * j,
                                                    acc[i][j], 132, wmma::mem_row_major);
                }
                __syncthreads();
                int r6 = tid >> 3;      // 0..63
                int part = tid & 7;     // 16 elems
                int gr = row0 + hh * 64 + r6;
                if (gr < NN) {
                    const float* srow = scr + r6 * 132 + part * 16;
                    uint32_t hp[8], lp[8];
                    #pragma unroll
                    for (int q = 0; q < 8; q++) {
                        __nv_bfloat16 h0, l0, h1, l1;
                        split_bf(srow[2 * q], h0, l0);
                        split_bf(srow[2 * q + 1], h1, l1);
                        hp[q] = bfpack(h0, h1);
                        lp[q] = bfpack(l0, l1);
                    }
                    size_t off = (size_t)gr * DH + part * 16;
                    *reinterpret_cast<uint4*>(outhi + off)     = *reinterpret_cast<uint4*>(hp);
                    *reinterpret_cast<uint4*>(outhi + off + 8) = *reinterpret_cast<uint4*>(hp + 4);
                    *reinterpret_cast<uint4*>(outlo + off)     = *reinterpret_cast<uint4*>(lp);
                    *reinterpret_cast<uint4*>(outlo + off + 8) = *reinterpret_cast<uint4*>(lp + 4);
                }
            }
            __syncthreads();
        } else {
            if (row0 + 128 <= NN) {
                #pragma unroll
                for (int i = 0; i < 2; i++)
                    #pragma unroll
                    for (int j = 0; j < 2; j++)
                        wmma::store_matrix_sync(foutv + (size_t)(row0 + 32 * wm + 16 * i) * DH + 32 * wn + 16 * j,
                                                acc[i][j], DH, wmma::mem_row_major);
            } else {
                #pragma unroll
                for (int i = 0; i < 2; i++)
                    #pragma unroll
                    for (int j = 0; j < 2; j++)
                        wmma::store_matrix_sync(tail + (size_t)(32 * wm + 16 * i) * DH + 32 * wn + 16 * j,
                                                acc[i][j], DH, wmma::mem_row_major);
                __syncthreads();
                if (grow < NN) {
                    const float* srow = tail + (size_t)r * DH + quarter * 32;
                    float* drow = foutv + (size_t)grow * DH + quarter * 32;
                    #pragma unroll
                    for (int q = 0; q < 8; q++)
                        *reinterpret_cast<float4*>(drow + q * 4) =
                            *reinterpret_cast<const float4*>(srow + q * 4);
                }
            }
            __syncthreads();
        }
    }
}

// ============ host ============
extern "C" void kernel_launch(void* const* d_in, const int* in_sizes, int n_in,
                              void* d_out, int out_size) {
    const float* x      = (const float*)d_in[0];
    const int*   ei     = (const int*)d_in[1];
    const float* ea     = (const float*)d_in[2];
    const float* Wrel1  = (const float*)d_in[3];
    const float* b1     = (const float*)d_in[4];
    const float* Wroot1 = (const float*)d_in[5];
    const float* Wrel2  = (const float*)d_in[6];
    const float* b2     = (const float*)d_in[7];
    const float* Wroot2 = (const float*)d_in[8];
    const float* Wrel3  = (const float*)d_in[9];
    const float* b3     = (const float*)d_in[10];
    const float* Wroot3 = (const float*)d_in[11];
    float* out = (float*)d_out;

    const int* src = ei;
    const int* dst = ei + NE;

    int *deg, *rowptr, *cursor;
    uint2 *csr;
    float *tail;
    __nv_bfloat16 *agghi, *agglo, *xhi, *xlo, *h1hi, *h1lo, *h2hi, *h2lo, *whi, *wlo;
    cudaGetSymbolAddress((void**)&deg,    g_deg);
    cudaGetSymbolAddress((void**)&rowptr, g_rowptr);
    cudaGetSymbolAddress((void**)&cursor, g_cursor);
    cudaGetSymbolAddress((void**)&csr,    g_csr);
    cudaGetSymbolAddress((void**)&agghi,  g_agghi);
    cudaGetSymbolAddress((void**)&agglo,  g_agglo);
    cudaGetSymbolAddress((void**)&xhi,    g_xhi);
    cudaGetSymbolAddress((void**)&xlo,    g_xlo);
    cudaGetSymbolAddress((void**)&h1hi,   g_h1hi);
    cudaGetSymbolAddress((void**)&h1lo,   g_h1lo);
    cudaGetSymbolAddress((void**)&h2hi,   g_h2hi);
    cudaGetSymbolAddress((void**)&h2lo,   g_h2lo);
    cudaGetSymbolAddress((void**)&tail,   g_tail);
    cudaGetSymbolAddress((void**)&whi,    g_whi);
    cudaGetSymbolAddress((void**)&wlo,    g_wlo);

    cudaFuncSetAttribute(gemm_persist_kernel,
                         cudaFuncAttributeMaxDynamicSharedMemorySize, GEMM_SMEM);

    // (1) fused prep: zero deg + split x + prep W  — no memset launch
    int prep_items = XQUADS + NN + WELEMS;
    prep_all_kernel<<<(prep_items + 255) / 256, 256>>>(
        x, Wrel1, Wroot1, Wrel2, Wroot2, Wrel3, Wroot3,
        xhi, xlo, whi, wlo, deg);
    // (2-4) CSR build
    deg_count_kernel<<<(NE + 255) / 256, 256>>>(dst, deg);
    scan_kernel<<<1, 1024>>>(deg, rowptr, cursor);
    fill_csr_kernel<<<(NE + 255) / 256, 256>>>(src, dst, ea, cursor, csr);

    const __nv_bfloat16* inhi[3] = {xhi, h1hi, h2hi};
    const __nv_bfloat16* inlo[3] = {xlo, h1lo, h2lo};
    __nv_bfloat16* ohi[3] = {h1hi, h2hi, nullptr};
    __nv_bfloat16* olo[3] = {h1lo, h2lo, nullptr};
    const float* bv[3] = {b1, b2, b3};

    int gather_blocks = (NN * 32 + 255) / 256;
    // (5,6,...) gather/gemm pairs — ncu capture lands here now
    for (int l = 0; l < 3; l++) {
        gather_agg_kernel<<<gather_blocks, 256>>>(inhi[l], inlo[l], rowptr, csr, agghi, agglo);
        gemm_persist_kernel<<<148, 512, GEMM_SMEM>>>(
            agghi, agglo, inhi[l], inlo[l],
            whi + l * 32768, wlo + l * 32768, bv[l],
            ohi[l], olo[l], out, tail, l == 2 ? 1 : 0);
    }
}

// round 11
// speedup vs baseline: 1.0299x; 1.0099x over previous
#include <cuda_runtime.h>
#include <cuda_bf16.h>
#include <mma.h>
#include <stdint.h>

using namespace nvcuda;

#define NN 100000
#define NE 1600000
#define DH 128
#define NT256 391    // ceil(NN/256)

// ---- scratch (device globals; no allocation allowed) ----
__device__ int   g_deg[NN];
__device__ int   g_rowptr[NN + 1];
__device__ int   g_cursor[NN];
__device__ uint2 g_csr[NE];
__device__ __nv_bfloat16 g_agghi[NN * DH];
__device__ __nv_bfloat16 g_agglo[NN * DH];
__device__ __nv_bfloat16 g_xhi[NN * DH];
__device__ __nv_bfloat16 g_xlo[NN * DH];
__device__ __nv_bfloat16 g_h1hi[NN * DH];
__device__ __nv_bfloat16 g_h1lo[NN * DH];
__device__ __nv_bfloat16 g_h2hi[NN * DH];
__device__ __nv_bfloat16 g_h2lo[NN * DH];
__device__ __nv_bfloat16 g_whi[3 * 256 * 128];
__device__ __nv_bfloat16 g_wlo[3 * 256 * 128];

// ============ small helpers ============
__device__ __forceinline__ uint32_t bfpack(__nv_bfloat16 a, __nv_bfloat16 b) {
    return (uint32_t)__bfloat16_as_ushort(a) | ((uint32_t)__bfloat16_as_ushort(b) << 16);
}
__device__ __forceinline__ void split_bf(float v, __nv_bfloat16& h, __nv_bfloat16& l) {
    h = __float2bfloat16_rn(v);
    l = __float2bfloat16_rn(v - __bfloat162float(h));
}
__device__ __forceinline__ float2 bf2f2(uint32_t u) {
    __nv_bfloat162 b = *reinterpret_cast<__nv_bfloat162*>(&u);
    return __bfloat1622float2(b);
}

// ============ fused prep: zero deg + split x + prep weights ============
#define XQUADS (NN * DH / 4)
#define WELEMS (3 * 256 * 128)
__global__ void prep_all_kernel(const float* __restrict__ x,
                                const float* __restrict__ Wrel1, const float* __restrict__ Wroot1,
                                const float* __restrict__ Wrel2, const float* __restrict__ Wroot2,
                                const float* __restrict__ Wrel3, const float* __restrict__ Wroot3,
                                __nv_bfloat16* __restrict__ xhi, __nv_bfloat16* __restrict__ xlo,
                                __nv_bfloat16* __restrict__ whi, __nv_bfloat16* __restrict__ wlo,
                                int* __restrict__ deg) {
    int i = blockIdx.x * blockDim.x + threadIdx.x;
    if (i < XQUADS) {
        float4 v = *reinterpret_cast<const float4*>(x + (size_t)i * 4);
        __nv_bfloat16 h0, l0, h1, l1, h2, l2, h3, l3;
        split_bf(v.x, h0, l0); split_bf(v.y, h1, l1);
        split_bf(v.z, h2, l2); split_bf(v.w, h3, l3);
        *reinterpret_cast<uint2*>(xhi + (size_t)i * 4) = make_uint2(bfpack(h0, h1), bfpack(h2, h3));
        *reinterpret_cast<uint2*>(xlo + (size_t)i * 4) = make_uint2(bfpack(l0, l1), bfpack(l2, l3));
    } else if (i < XQUADS + NN) {
        deg[i - XQUADS] = 0;
    } else if (i < XQUADS + NN + WELEMS) {
        int w = i - (XQUADS + NN);
        int l = w >> 15;
        int j = w & 32767;
        int k = j >> 7, n = j & 127;
        const float* Wrel  = (l == 0) ? Wrel1  : (l == 1) ? Wrel2  : Wrel3;
        const float* Wroot = (l == 0) ? Wroot1 : (l == 1) ? Wroot2 : Wroot3;
        float v = (k < 128) ? Wrel[k * 128 + n] : Wroot[(k - 128) * 128 + n];
        __nv_bfloat16 h, lw;
        split_bf(v, h, lw);
        whi[w] = h; wlo[w] = lw;
    }
}

// ============ CSR build ============
__global__ void deg_count_kernel(const int* __restrict__ dst, int* __restrict__ deg) {
    int i = blockIdx.x * blockDim.x + threadIdx.x;
    if (i < NE) atomicAdd(&deg[dst[i]], 1);
}

__global__ void scan_kernel(const int* __restrict__ deg,
                            int* __restrict__ rowptr, int* __restrict__ cursor) {
    __shared__ int wsum[32];
    __shared__ int carry;
    const int tid = threadIdx.x, lane = tid & 31, warp = tid >> 5;
    if (tid == 0) carry = 0;
    __syncthreads();
    for (int base = 0; base < NN; base += 1024) {
        int i = base + tid;
        int v = (i < NN) ? deg[i] : 0;
        int s = v;
        #pragma unroll
        for (int off = 1; off < 32; off <<= 1) {
            int t = __shfl_up_sync(0xFFFFFFFF, s, off);
            if (lane >= off) s += t;
        }
        if (lane == 31) wsum[warp] = s;
        __syncthreads();
        if (warp == 0) {
            int w = wsum[lane];
            #pragma unroll
            for (int off = 1; off < 32; off <<= 1) {
                int t = __shfl_up_sync(0xFFFFFFFF, w, off);
                if (lane >= off) w += t;
            }
            wsum[lane] = w;
        }
        __syncthreads();
        int excl = s - v + (warp > 0 ? wsum[warp - 1] : 0) + carry;
        if (i < NN) { rowptr[i] = excl; cursor[i] = excl; }
        __syncthreads();
        if (tid == 0) carry += wsum[31];
        __syncthreads();
    }
    if (threadIdx.x == 0) rowptr[NN] = carry;
}

__global__ void fill_csr_kernel(const int* __restrict__ src, const int* __restrict__ dst,
                                const float* __restrict__ w, int* __restrict__ cursor,
                                uint2* __restrict__ csr) {
    int e = blockIdx.x * blockDim.x + threadIdx.x;
    if (e < NE) {
        int d = dst[e];
        int p = atomicAdd(&cursor[d], 1);
        csr[p] = make_uint2((unsigned)src[e], __float_as_uint(w[e]));
    }
}

// ============ aggregation ============
__global__ void gather_agg_kernel(const __nv_bfloat16* __restrict__ inhi,
                                  const __nv_bfloat16* __restrict__ inlo,
                                  const int* __restrict__ rowptr,
                                  const uint2* __restrict__ csr,
                                  __nv_bfloat16* __restrict__ agghi,
                                  __nv_bfloat16* __restrict__ agglo) {
    unsigned gt = blockIdx.x * blockDim.x + threadIdx.x;
    unsigned node = gt >> 5;
    int lane = threadIdx.x & 31;
    if (node >= NN) return;
    int s0 = __ldg(rowptr + node);
    int s1 = __ldg(rowptr + node + 1);
    float4 acc = make_float4(0.f, 0.f, 0.f, 0.f);
    int e = s0;
    for (; e + 1 < s1; e += 2) {
        uint2 e0 = __ldg(csr + e);
        uint2 e1 = __ldg(csr + e + 1);
        size_t o0 = (size_t)e0.x * DH + lane * 4;
        size_t o1 = (size_t)e1.x * DH + lane * 4;
        uint2 h0 = *reinterpret_cast<const uint2*>(inhi + o0);
        uint2 l0 = *reinterpret_cast<const uint2*>(inlo + o0);
        uint2 h1 = *reinterpret_cast<const uint2*>(inhi + o1);
        uint2 l1 = *reinterpret_cast<const uint2*>(inlo + o1);
        float w0 = __uint_as_float(e0.y), w1 = __uint_as_float(e1.y);
        float2 a, b;
        a = bf2f2(h0.x); b = bf2f2(l0.x);
        acc.x = fmaf(w0, a.x + b.x, acc.x); acc.y = fmaf(w0, a.y + b.y, acc.y);
        a = bf2f2(h0.y); b = bf2f2(l0.y);
        acc.z = fmaf(w0, a.x + b.x, acc.z); acc.w = fmaf(w0, a.y + b.y, acc.w);
        a = bf2f2(h1.x); b = bf2f2(l1.x);
        acc.x = fmaf(w1, a.x + b.x, acc.x); acc.y = fmaf(w1, a.y + b.y, acc.y);
        a = bf2f2(h1.y); b = bf2f2(l1.y);
        acc.z = fmaf(w1, a.x + b.x, acc.z); acc.w = fmaf(w1, a.y + b.y, acc.w);
    }
    if (e < s1) {
        uint2 e0 = __ldg(csr + e);
        size_t o0 = (size_t)e0.x * DH + lane * 4;
        uint2 h0 = *reinterpret_cast<const uint2*>(inhi + o0);
        uint2 l0 = *reinterpret_cast<const uint2*>(inlo + o0);
        float w0 = __uint_as_float(e0.y);
        float2 a, b;
        a = bf2f2(h0.x); b = bf2f2(l0.x);
        acc.x = fmaf(w0, a.x + b.x, acc.x); acc.y = fmaf(w0, a.y + b.y, acc.y);
        a = bf2f2(h0.y); b = bf2f2(l0.y);
        acc.z = fmaf(w0, a.x + b.x, acc.z); acc.w = fmaf(w0, a.y + b.y, acc.w);
    }
    float di = (s1 > s0) ? 1.0f / (float)(s1 - s0) : 0.f;
    acc.x *= di; acc.y *= di; acc.z *= di; acc.w *= di;

    __nv_bfloat16 h0, l0, h1, l1, h2, l2, h3, l3;
    split_bf(acc.x, h0, l0); split_bf(acc.y, h1, l1);
    split_bf(acc.z, h2, l2); split_bf(acc.w, h3, l3);
    size_t off = (size_t)node * DH + lane * 4;
    *reinterpret_cast<uint2*>(agghi + off) = make_uint2(bfpack(h0, h1), bfpack(h2, h3));
    *reinterpret_cast<uint2*>(agglo + off) = make_uint2(bfpack(l0, l1), bfpack(l2, l3));
}

// ============ persistent wmma GEMM: 256x128 tiles ============
// 148 CTAs x 512 threads = 16 warps as 8(row)x2(col); warp tile 32x64, acc[2][4].
// B hi/lo resident (stride 136). A: 16 chunks of 256x16, 3-stage cp.async ring.
#define BSTR 136
#define ASTR 24                              // 16k + pad (48B rows, LDSM conflict-free)
#define OFF_BH 0u
#define OFF_BL 69632u
#define OFF_BB 139264u                       // bias B: 16 x BSTR x bf16 = 4352
#define OFF_AB 143616u                       // bias A: 16 x ASTR x bf16 = 768 (all rows same)
#define OFF_A  144896u                       // 3 stages x (AH 12288 + AL 12288)
#define ASTAGE 24576u
#define GEMM_SMEM (144896 + 3 * 24576)       // 218624

__global__ void __launch_bounds__(512, 1) gemm_persist_kernel(
    const __nv_bfloat16* __restrict__ agghi, const __nv_bfloat16* __restrict__ agglo,
    const __nv_bfloat16* __restrict__ xhi,   const __nv_bfloat16* __restrict__ xlo,
    const __nv_bfloat16* __restrict__ whi,   const __nv_bfloat16* __restrict__ wlo,
    const float* __restrict__ bias,
    __nv_bfloat16* __restrict__ outhi, __nv_bfloat16* __restrict__ outlo,
    float* __restrict__ foutv, int final_layer)
{
    extern __shared__ char smem[];
    __nv_bfloat16* BH = reinterpret_cast<__nv_bfloat16*>(smem + OFF_BH);
    __nv_bfloat16* BL = reinterpret_cast<__nv_bfloat16*>(smem + OFF_BL);
    __nv_bfloat16* BB = reinterpret_cast<__nv_bfloat16*>(smem + OFF_BB);
    __nv_bfloat16* AB = reinterpret_cast<__nv_bfloat16*>(smem + OFF_AB);
    uint32_t smemA;
    {
        uint32_t a;
        asm("{ .reg .u64 t; cvta.to.shared.u64 t, %1; cvt.u32.u64 %0, t; }" : "=r"(a) : "l"(smem + OFF_A));
        smemA = a;
    }

    const int tid = threadIdx.x;
    const int wid = tid >> 5;
    const int wm = wid >> 1;      // 0..7 -> rows 32*wm
    const int wn = wid & 1;       // 0..1 -> cols 64*wn

    // one-time staging: B hi/lo, bias chunks
    #pragma unroll
    for (int j = 0; j < 8; j++) {
        int f = tid + j * 512;
        int rr = f >> 4, c8 = f & 15;
        uint4 vh = *reinterpret_cast<const uint4*>(whi + (size_t)rr * 128 + c8 * 8);
        uint4 vl = *reinterpret_cast<const uint4*>(wlo + (size_t)rr * 128 + c8 * 8);
        *reinterpret_cast<uint4*>(BH + rr * BSTR + c8 * 8) = vh;
        *reinterpret_cast<uint4*>(BL + rr * BSTR + c8 * 8) = vl;
    }
    for (int i = tid; i < (16 * BSTR + 16 * ASTR) / 2; i += 512)
        reinterpret_cast<uint32_t*>(BB)[i] = 0;   // BB then AB contiguous
    __syncthreads();
    if (tid < 128) {
        __nv_bfloat16 h, l;
        split_bf(bias[tid], h, l);
        BB[0 * BSTR + tid] = h;
        BB[1 * BSTR + tid] = l;
        if (tid < 16) {
            AB[tid * ASTR + 0] = __float2bfloat16_rn(1.0f);
            AB[tid * ASTR + 1] = __float2bfloat16_rn(1.0f);
        }
    }
    __syncthreads();

    for (int tile = blockIdx.x; tile < NT256; tile += 148) {
        const int row0 = tile * 256;
        const int arow = tid >> 1;            // 0..255
        const int aseg = tid & 1;             // 8 bf16 = 16B each
        const int grow = row0 + arow;
        const int sz = (grow < NN) ? 16 : 0;

        auto issue = [&](int c) {
            const __nv_bfloat16* ph = (c < 8) ? agghi : xhi;
            const __nv_bfloat16* pl = (c < 8) ? agglo : xlo;
            const int k0 = (c & 7) * 16;
            const __nv_bfloat16* sh = ph + (size_t)grow * DH + k0 + aseg * 8;
            const __nv_bfloat16* sl = pl + (size_t)grow * DH + k0 + aseg * 8;
            uint32_t dh = smemA + (uint32_t)(c % 3) * ASTAGE + (uint32_t)(arow * ASTR + aseg * 8) * 2u;
            uint32_t dl = dh + 12288u;
            asm volatile("cp.async.cg.shared.global [%0], [%1], 16, %2;" :: "r"(dh), "l"(sh), "r"(sz));
            asm volatile("cp.async.cg.shared.global [%0], [%1], 16, %2;" :: "r"(dl), "l"(sl), "r"(sz));
            asm volatile("cp.async.commit_group;");
        };

        wmma::fragment<wmma::accumulator, 16, 16, 16, float> acc[2][4];
        #pragma unroll
        for (int i = 0; i < 2; i++)
            #pragma unroll
            for (int j = 0; j < 4; j++) wmma::fill_fragment(acc[i][j], 0.f);

        // bias rank-1 chunk (fa identical for both row-frags)
        {
            wmma::fragment<wmma::matrix_a, 16, 16, 16, __nv_bfloat16, wmma::row_major> fa;
            wmma::load_matrix_sync(fa, AB, ASTR);
            #pragma unroll
            for (int j = 0; j < 4; j++) {
                wmma::fragment<wmma::matrix_b, 16, 16, 16, __nv_bfloat16, wmma::row_major> fb;
                wmma::load_matrix_sync(fb, BB + 64 * wn + 16 * j, BSTR);
                #pragma unroll
                for (int i = 0; i < 2; i++)
                    wmma::mma_sync(acc[i][j], fa, fb, acc[i][j]);
            }
        }

        issue(0);

        #pragma unroll 1
        for (int c = 0; c < 16; c++) {
            if (c < 15) {
                issue(c + 1);
                asm volatile("cp.async.wait_group 1;");
            } else {
                asm volatile("cp.async.wait_group 0;");
            }
            __syncthreads();
            const __nv_bfloat16* AHc = reinterpret_cast<const __nv_bfloat16*>(smem + OFF_A + (c % 3) * ASTAGE);
            const __nv_bfloat16* ALc = AHc + 6144;   // 12288 bytes
            const int krow = c * 16;
            wmma::fragment<wmma::matrix_b, 16, 16, 16, __nv_bfloat16, wmma::row_major> fbh[4], fbl[4];
            #pragma unroll
            for (int j = 0; j < 4; j++) {
                wmma::load_matrix_sync(fbh[j], BH + krow * BSTR + 64 * wn + 16 * j, BSTR);
                wmma::load_matrix_sync(fbl[j], BL + krow * BSTR + 64 * wn + 16 * j, BSTR);
            }
            #pragma unroll
            for (int i = 0; i < 2; i++) {
                wmma::fragment<wmma::matrix_a, 16, 16, 16, __nv_bfloat16, wmma::row_major> fah, fal;
                wmma::load_matrix_sync(fah, AHc + (32 * wm + 16 * i) * ASTR, ASTR);
                wmma::load_matrix_sync(fal, ALc + (32 * wm + 16 * i) * ASTR, ASTR);
                #pragma unroll
                for (int j = 0; j < 4; j++) {
                    wmma::mma_sync(acc[i][j], fah, fbh[j], acc[i][j]);
                    wmma::mma_sync(acc[i][j], fah, fbl[j], acc[i][j]);
                    wmma::mma_sync(acc[i][j], fal, fbh[j], acc[i][j]);
                }
            }
        }

        // relu
        #pragma unroll
        for (int i = 0; i < 2; i++)
            #pragma unroll
            for (int j = 0; j < 4; j++)
                #pragma unroll
                for (int e = 0; e < acc[i][j].num_elements; e++)
                    acc[i][j].x[e] = fmaxf(acc[i][j].x[e], 0.f);

        if (final_layer && row0 + 256 <= NN) {
            #pragma unroll
            for (int i = 0; i < 2; i++)
                #pragma unroll
                for (int j = 0; j < 4; j++)
                    wmma::store_matrix_sync(foutv + (size_t)(row0 + 32 * wm + 16 * i) * DH + 64 * wn + 16 * j,
                                            acc[i][j], DH, wmma::mem_row_major);
            __syncthreads();
        } else {
            // smem roundtrip in 4 phases of 64 rows (scratch = A region, 64x132 f32)
            float* scr = reinterpret_cast<float*>(smem + OFF_A);
            #pragma unroll 1
            for (int hh = 0; hh < 4; hh++) {
                __syncthreads();
                if ((wm >> 1) == hh) {
                    int lr = 32 * (wm & 1);
                    #pragma unroll
                    for (int i = 0; i < 2; i++)
                        #pragma unroll
                        for (int j = 0; j < 4; j++)
                            wmma::store_matrix_sync(scr + (lr + 16 * i) * 132 + 64 * wn + 16 * j,
                                                    acc[i][j], 132, wmma::mem_row_major);
                }
                __syncthreads();
                int r6 = tid >> 3;      // 0..63
                int part = tid & 7;     // 16 elems
                int gr = row0 + hh * 64 + r6;
                if (gr < NN) {
                    const float* srow = scr + r6 * 132 + part * 16;
                    if (!final_layer) {
                        uint32_t hp[8], lp[8];
                        #pragma unroll
                        for (int q = 0; q < 8; q++) {
                            __nv_bfloat16 h0, l0, h1, l1;
                            split_bf(srow[2 * q], h0, l0);
                            split_bf(srow[2 * q + 1], h1, l1);
                            hp[q] = bfpack(h0, h1);
                            lp[q] = bfpack(l0, l1);
                        }
                        size_t off = (size_t)gr * DH + part * 16;
                        *reinterpret_cast<uint4*>(outhi + off)     = *reinterpret_cast<uint4*>(hp);
                        *reinterpret_cast<uint4*>(outhi + off + 8) = *reinterpret_cast<uint4*>(hp + 4);
                        *reinterpret_cast<uint4*>(outlo + off)     = *reinterpret_cast<uint4*>(lp);
                        *reinterpret_cast<uint4*>(outlo + off + 8) = *reinterpret_cast<uint4*>(lp + 4);
                    } else {
                        float* drow = foutv + (size_t)gr * DH + part * 16;
                        #pragma unroll
                        for (int q = 0; q < 4; q++)
                            *reinterpret_cast<float4*>(drow + q * 4) =
                                *reinterpret_cast<const float4*>(srow + q * 4);
                    }
                }
            }
            __syncthreads();   // scratch becomes A ring again next tile
        }
    }
}

// ============ host ============
extern "C" void kernel_launch(void* const* d_in, const int* in_sizes, int n_in,
                              void* d_out, int out_size) {
    const float* x      = (const float*)d_in[0];
    const int*   ei     = (const int*)d_in[1];
    const float* ea     = (const float*)d_in[2];
    const float* Wrel1  = (const float*)d_in[3];
    const float* b1     = (const float*)d_in[4];
    const float* Wroot1 = (const float*)d_in[5];
    const float* Wrel2  = (const float*)d_in[6];
    const float* b2     = (const float*)d_in[7];
    const float* Wroot2 = (const float*)d_in[8];
    const float* Wrel3  = (const float*)d_in[9];
    const float* b3     = (const float*)d_in[10];
    const float* Wroot3 = (const float*)d_in[11];
    float* out = (float*)d_out;

    const int* src = ei;
    const int* dst = ei + NE;

    int *deg, *rowptr, *cursor;
    uint2 *csr;
    __nv_bfloat16 *agghi, *agglo, *xhi, *xlo, *h1hi, *h1lo, *h2hi, *h2lo, *whi, *wlo;
    cudaGetSymbolAddress((void**)&deg,    g_deg);
    cudaGetSymbolAddress((void**)&rowptr, g_rowptr);
    cudaGetSymbolAddress((void**)&cursor, g_cursor);
    cudaGetSymbolAddress((void**)&csr,    g_csr);
    cudaGetSymbolAddress((void**)&agghi,  g_agghi);
    cudaGetSymbolAddress((void**)&agglo,  g_agglo);
    cudaGetSymbolAddress((void**)&xhi,    g_xhi);
    cudaGetSymbolAddress((void**)&xlo,    g_xlo);
    cudaGetSymbolAddress((void**)&h1hi,   g_h1hi);
    cudaGetSymbolAddress((void**)&h1lo,   g_h1lo);
    cudaGetSymbolAddress((void**)&h2hi,   g_h2hi);
    cudaGetSymbolAddress((void**)&h2lo,   g_h2lo);
    cudaGetSymbolAddress((void**)&whi,    g_whi);
    cudaGetSymbolAddress((void**)&wlo,    g_wlo);

    cudaFuncSetAttribute(gemm_persist_kernel,
                         cudaFuncAttributeMaxDynamicSharedMemorySize, GEMM_SMEM);

    int prep_items = XQUADS + NN + WELEMS;
    prep_all_kernel<<<(prep_items + 255) / 256, 256>>>(
        x, Wrel1, Wroot1, Wrel2, Wroot2, Wrel3, Wroot3,
        xhi, xlo, whi, wlo, deg);
    deg_count_kernel<<<(NE + 255) / 256, 256>>>(dst, deg);
    scan_kernel<<<1, 1024>>>(deg, rowptr, cursor);
    fill_csr_kernel<<<(NE + 255) / 256, 256>>>(src, dst, ea, cursor, csr);

    const __nv_bfloat16* inhi[3] = {xhi, h1hi, h2hi};
    const __nv_bfloat16* inlo[3] = {xlo, h1lo, h2lo};
    __nv_bfloat16* ohi[3] = {h1hi, h2hi, nullptr};
    __nv_bfloat16* olo[3] = {h1lo, h2lo, nullptr};
    const float* bv[3] = {b1, b2, b3};

    int gather_blocks = (NN * 32 + 255) / 256;
    for (int l = 0; l < 3; l++) {
        gather_agg_kernel<<<gather_blocks, 256>>>(inhi[l], inlo[l], rowptr, csr, agghi, agglo);
        gemm_persist_kernel<<<148, 512, GEMM_SMEM>>>(
            agghi, agglo, inhi[l], inlo[l],
            whi + l * 32768, wlo + l * 32768, bv[l],
            ohi[l], olo[l], out, l == 2 ? 1 : 0);
    }
}

// round 12
// speedup vs baseline: 1.2467x; 1.2105x over previous
#include <cuda_runtime.h>
#include <cuda_fp16.h>
#include <mma.h>
#include <stdint.h>

using namespace nvcuda;

#define NN 100000
#define NE 1600000
#define DH 128
#define NT256 391    // ceil(NN/256)

// ---- scratch (device globals; no allocation allowed) ----
__device__ int   g_deg[NN];
__device__ int   g_rowptr[NN + 1];
__device__ int   g_cursor[NN];
__device__ uint2 g_csr[NE];
__device__ __half g_agghi[NN * DH];
__device__ __half g_agglo[NN * DH];
__device__ __half g_xhi[NN * DH];
__device__ __half g_xlo[NN * DH];
__device__ __half g_h1hi[NN * DH];
__device__ __half g_h1lo[NN * DH];
__device__ __half g_h2hi[NN * DH];
__device__ __half g_h2lo[NN * DH];
__device__ __half g_whi[3 * 256 * 128];   // [layer][k][n] fp16 hi plane only

// ============ small helpers ============
__device__ __forceinline__ uint32_t hpack(__half a, __half b) {
    return (uint32_t)__half_as_ushort(a) | ((uint32_t)__half_as_ushort(b) << 16);
}
__device__ __forceinline__ void split_h(float v, __half& h, __half& l) {
    h = __float2half_rn(v);
    l = __float2half_rn(v - __half2float(h));
}
__device__ __forceinline__ float2 h2f2(uint32_t u) {
    __half2 b = *reinterpret_cast<__half2*>(&u);
    return __half22float2(b);
}

// ============ fused prep: zero deg + split x + prep weights ============
#define XQUADS (NN * DH / 4)
#define WELEMS (3 * 256 * 128)
__global__ void prep_all_kernel(const float* __restrict__ x,
                                const float* __restrict__ Wrel1, const float* __restrict__ Wroot1,
                                const float* __restrict__ Wrel2, const float* __restrict__ Wroot2,
                                const float* __restrict__ Wrel3, const float* __restrict__ Wroot3,
                                __half* __restrict__ xhi, __half* __restrict__ xlo,
                                __half* __restrict__ whi,
                                int* __restrict__ deg) {
    int i = blockIdx.x * blockDim.x + threadIdx.x;
    if (i < XQUADS) {
        float4 v = *reinterpret_cast<const float4*>(x + (size_t)i * 4);
        __half h0, l0, h1, l1, h2, l2, h3, l3;
        split_h(v.x, h0, l0); split_h(v.y, h1, l1);
        split_h(v.z, h2, l2); split_h(v.w, h3, l3);
        *reinterpret_cast<uint2*>(xhi + (size_t)i * 4) = make_uint2(hpack(h0, h1), hpack(h2, h3));
        *reinterpret_cast<uint2*>(xlo + (size_t)i * 4) = make_uint2(hpack(l0, l1), hpack(l2, l3));
    } else if (i < XQUADS + NN) {
        deg[i - XQUADS] = 0;
    } else if (i < XQUADS + NN + WELEMS) {
        int w = i - (XQUADS + NN);
        int l = w >> 15;
        int j = w & 32767;
        int k = j >> 7, n = j & 127;
        const float* Wrel  = (l == 0) ? Wrel1  : (l == 1) ? Wrel2  : Wrel3;
        const float* Wroot = (l == 0) ? Wroot1 : (l == 1) ? Wroot2 : Wroot3;
        float v = (k < 128) ? Wrel[k * 128 + n] : Wroot[(k - 128) * 128 + n];
        whi[w] = __float2half_rn(v);
    }
}

// ============ CSR build ============
__global__ void deg_count_kernel(const int* __restrict__ dst, int* __restrict__ deg) {
    int i = blockIdx.x * blockDim.x + threadIdx.x;
    if (i < NE) atomicAdd(&deg[dst[i]], 1);
}

__global__ void scan_kernel(const int* __restrict__ deg,
                            int* __restrict__ rowptr, int* __restrict__ cursor) {
    __shared__ int wsum[32];
    __shared__ int carry;
    const int tid = threadIdx.x, lane = tid & 31, warp = tid >> 5;
    if (tid == 0) carry = 0;
    __syncthreads();
    for (int base = 0; base < NN; base += 1024) {
        int i = base + tid;
        int v = (i < NN) ? deg[i] : 0;
        int s = v;
        #pragma unroll
        for (int off = 1; off < 32; off <<= 1) {
            int t = __shfl_up_sync(0xFFFFFFFF, s, off);
            if (lane >= off) s += t;
        }
        if (lane == 31) wsum[warp] = s;
        __syncthreads();
        if (warp == 0) {
            int w = wsum[lane];
            #pragma unroll
            for (int off = 1; off < 32; off <<= 1) {
                int t = __shfl_up_sync(0xFFFFFFFF, w, off);
                if (lane >= off) w += t;
            }
            wsum[lane] = w;
        }
        __syncthreads();
        int excl = s - v + (warp > 0 ? wsum[warp - 1] : 0) + carry;
        if (i < NN) { rowptr[i] = excl; cursor[i] = excl; }
        __syncthreads();
        if (tid == 0) carry += wsum[31];
        __syncthreads();
    }
    if (threadIdx.x == 0) rowptr[NN] = carry;
}

__global__ void fill_csr_kernel(const int* __restrict__ src, const int* __restrict__ dst,
                                const float* __restrict__ w, int* __restrict__ cursor,
                                uint2* __restrict__ csr) {
    int e = blockIdx.x * blockDim.x + threadIdx.x;
    if (e < NE) {
        int d = dst[e];
        int p = atomicAdd(&cursor[d], 1);
        csr[p] = make_uint2((unsigned)src[e], __float_as_uint(w[e]));
    }
}

// ============ aggregation: one warp per node; fp16 hi/lo planes ============
__global__ void gather_agg_kernel(const __half* __restrict__ inhi,
                                  const __half* __restrict__ inlo,
                                  const int* __restrict__ rowptr,
                                  const uint2* __restrict__ csr,
                                  __half* __restrict__ agghi,
                                  __half* __restrict__ agglo) {
    unsigned gt = blockIdx.x * blockDim.x + threadIdx.x;
    unsigned node = gt >> 5;
    int lane = threadIdx.x & 31;
    if (node >= NN) return;
    int s0 = __ldg(rowptr + node);
    int s1 = __ldg(rowptr + node + 1);
    float4 acc = make_float4(0.f, 0.f, 0.f, 0.f);
    int e = s0;
    for (; e + 1 < s1; e += 2) {
        uint2 e0 = __ldg(csr + e);
        uint2 e1 = __ldg(csr + e + 1);
        size_t o0 = (size_t)e0.x * DH + lane * 4;
        size_t o1 = (size_t)e1.x * DH + lane * 4;
        uint2 h0 = *reinterpret_cast<const uint2*>(inhi + o0);
        uint2 l0 = *reinterpret_cast<const uint2*>(inlo + o0);
        uint2 h1 = *reinterpret_cast<const uint2*>(inhi + o1);
        uint2 l1 = *reinterpret_cast<const uint2*>(inlo + o1);
        float w0 = __uint_as_float(e0.y), w1 = __uint_as_float(e1.y);
        float2 a, b;
        a = h2f2(h0.x); b = h2f2(l0.x);
        acc.x = fmaf(w0, a.x + b.x, acc.x); acc.y = fmaf(w0, a.y + b.y, acc.y);
        a = h2f2(h0.y); b = h2f2(l0.y);
        acc.z = fmaf(w0, a.x + b.x, acc.z); acc.w = fmaf(w0, a.y + b.y, acc.w);
        a = h2f2(h1.x); b = h2f2(l1.x);
        acc.x = fmaf(w1, a.x + b.x, acc.x); acc.y = fmaf(w1, a.y + b.y, acc.y);
        a = h2f2(h1.y); b = h2f2(l1.y);
        acc.z = fmaf(w1, a.x + b.x, acc.z); acc.w = fmaf(w1, a.y + b.y, acc.w);
    }
    if (e < s1) {
        uint2 e0 = __ldg(csr + e);
        size_t o0 = (size_t)e0.x * DH + lane * 4;
        uint2 h0 = *reinterpret_cast<const uint2*>(inhi + o0);
        uint2 l0 = *reinterpret_cast<const uint2*>(inlo + o0);
        float w0 = __uint_as_float(e0.y);
        float2 a, b;
        a = h2f2(h0.x); b = h2f2(l0.x);
        acc.x = fmaf(w0, a.x + b.x, acc.x); acc.y = fmaf(w0, a.y + b.y, acc.y);
        a = h2f2(h0.y); b = h2f2(l0.y);
        acc.z = fmaf(w0, a.x + b.x, acc.z); acc.w = fmaf(w0, a.y + b.y, acc.w);
    }
    float di = (s1 > s0) ? 1.0f / (float)(s1 - s0) : 0.f;
    acc.x *= di; acc.y *= di; acc.z *= di; acc.w *= di;

    __half h0, l0, h1, l1, h2, l2, h3, l3;
    split_h(acc.x, h0, l0); split_h(acc.y, h1, l1);
    split_h(acc.z, h2, l2); split_h(acc.w, h3, l3);
    size_t off = (size_t)node * DH + lane * 4;
    *reinterpret_cast<uint2*>(agghi + off) = make_uint2(hpack(h0, h1), hpack(h2, h3));
    *reinterpret_cast<uint2*>(agglo + off) = make_uint2(hpack(l0, l1), hpack(l2, l3));
}

// ============ persistent wmma GEMM: 256x128 tiles, fp16 2-product ============
// 16 warps as 8(row)x2(col); warp tile 32x64, acc[2][4]. B single fp16 plane resident.
// A: 16 chunks of 256x16 (hi+lo), 3-stage cp.async ring.
#define BSTR 136
#define ASTR 24
#define OFF_BH 0u                            // 256 x BSTR x 2 = 69632
#define OFF_BB 69632u                        // bias B: 16 x BSTR x 2 = 4352
#define OFF_AB 73984u                        // bias A: 16 x ASTR x 2 = 768
#define OFF_A  74752u                        // 3 stages x (AH 12288 + AL 12288)
#define ASTAGE 24576u
#define GEMM_SMEM (74752 + 3 * 24576)        // 148480

__global__ void __launch_bounds__(512, 1) gemm_persist_kernel(
    const __half* __restrict__ agghi, const __half* __restrict__ agglo,
    const __half* __restrict__ xhi,   const __half* __restrict__ xlo,
    const __half* __restrict__ whi,
    const float* __restrict__ bias,
    __half* __restrict__ outhi, __half* __restrict__ outlo,
    float* __restrict__ foutv, int final_layer)
{
    extern __shared__ char smem[];
    __half* BH = reinterpret_cast<__half*>(smem + OFF_BH);
    __half* BB = reinterpret_cast<__half*>(smem + OFF_BB);
    __half* AB = reinterpret_cast<__half*>(smem + OFF_AB);
    uint32_t smemA;
    {
        uint32_t a;
        asm("{ .reg .u64 t; cvta.to.shared.u64 t, %1; cvt.u32.u64 %0, t; }" : "=r"(a) : "l"(smem + OFF_A));
        smemA = a;
    }

    const int tid = threadIdx.x;
    const int wid = tid >> 5;
    const int wm = wid >> 1;      // 0..7 -> rows 32*wm
    const int wn = wid & 1;       // 0..1 -> cols 64*wn

    // one-time staging: B plane, bias chunks
    #pragma unroll
    for (int j = 0; j < 8; j++) {
        int f = tid + j * 512;
        int rr = f >> 4, c8 = f & 15;
        uint4 vh = *reinterpret_cast<const uint4*>(whi + (size_t)rr * 128 + c8 * 8);
        *reinterpret_cast<uint4*>(BH + rr * BSTR + c8 * 8) = vh;
    }
    for (int i = tid; i < (16 * BSTR + 16 * ASTR) / 2; i += 512)
        reinterpret_cast<uint32_t*>(BB)[i] = 0;   // BB then AB contiguous
    __syncthreads();
    if (tid < 128) {
        __half h, l;
        split_h(bias[tid], h, l);
        BB[0 * BSTR + tid] = h;
        BB[1 * BSTR + tid] = l;
        if (tid < 16) {
            AB[tid * ASTR + 0] = __float2half_rn(1.0f);
            AB[tid * ASTR + 1] = __float2half_rn(1.0f);
        }
    }
    __syncthreads();

    for (int tile = blockIdx.x; tile < NT256; tile += 148) {
        const int row0 = tile * 256;
        const int arow = tid >> 1;            // 0..255
        const int aseg = tid & 1;             // 8 fp16 = 16B each
        const int grow = row0 + arow;
        const int sz = (grow < NN) ? 16 : 0;

        auto issue = [&](int c) {
            const __half* ph = (c < 8) ? agghi : xhi;
            const __half* pl = (c < 8) ? agglo : xlo;
            const int k0 = (c & 7) * 16;
            const __half* sh = ph + (size_t)grow * DH + k0 + aseg * 8;
            const __half* sl = pl + (size_t)grow * DH + k0 + aseg * 8;
            uint32_t dh = smemA + (uint32_t)(c % 3) * ASTAGE + (uint32_t)(arow * ASTR + aseg * 8) * 2u;
            uint32_t dl = dh + 12288u;
            asm volatile("cp.async.cg.shared.global [%0], [%1], 16, %2;" :: "r"(dh), "l"(sh), "r"(sz));
            asm volatile("cp.async.cg.shared.global [%0], [%1], 16, %2;" :: "r"(dl), "l"(sl), "r"(sz));
            asm volatile("cp.async.commit_group;");
        };

        wmma::fragment<wmma::accumulator, 16, 16, 16, float> acc[2][4];
        #pragma unroll
        for (int i = 0; i < 2; i++)
            #pragma unroll
            for (int j = 0; j < 4; j++) wmma::fill_fragment(acc[i][j], 0.f);

        // bias rank-1 chunk
        {
            wmma::fragment<wmma::matrix_a, 16, 16, 16, __half, wmma::row_major> fa;
            wmma::load_matrix_sync(fa, AB, ASTR);
            #pragma unroll
            for (int j = 0; j < 4; j++) {
                wmma::fragment<wmma::matrix_b, 16, 16, 16, __half, wmma::row_major> fb;
                wmma::load_matrix_sync(fb, BB + 64 * wn + 16 * j, BSTR);
                #pragma unroll
                for (int i = 0; i < 2; i++)
                    wmma::mma_sync(acc[i][j], fa, fb, acc[i][j]);
            }
        }

        issue(0);

        #pragma unroll 1
        for (int c = 0; c < 16; c++) {
            if (c < 15) {
                issue(c + 1);
                asm volatile("cp.async.wait_group 1;");
            } else {
                asm volatile("cp.async.wait_group 0;");
            }
            __syncthreads();
            const __half* AHc = reinterpret_cast<const __half*>(smem + OFF_A + (c % 3) * ASTAGE);
            const __half* ALc = AHc + 6144;   // 12288 bytes
            const int krow = c * 16;
            wmma::fragment<wmma::matrix_b, 16, 16, 16, __half, wmma::row_major> fbh[4];
            #pragma unroll
            for (int j = 0; j < 4; j++)
                wmma::load_matrix_sync(fbh[j], BH + krow * BSTR + 64 * wn + 16 * j, BSTR);
            #pragma unroll
            for (int i = 0; i < 2; i++) {
                wmma::fragment<wmma::matrix_a, 16, 16, 16, __half, wmma::row_major> fah, fal;
                wmma::load_matrix_sync(fah, AHc + (32 * wm + 16 * i) * ASTR, ASTR);
                wmma::load_matrix_sync(fal, ALc + (32 * wm + 16 * i) * ASTR, ASTR);
                #pragma unroll
                for (int j = 0; j < 4; j++) {
                    wmma::mma_sync(acc[i][j], fah, fbh[j], acc[i][j]);
                    wmma::mma_sync(acc[i][j], fal, fbh[j], acc[i][j]);
                }
            }
        }

        // relu
        #pragma unroll
        for (int i = 0; i < 2; i++)
            #pragma unroll
            for (int j = 0; j < 4; j++)
                #pragma unroll
                for (int e = 0; e < acc[i][j].num_elements; e++)
                    acc[i][j].x[e] = fmaxf(acc[i][j].x[e], 0.f);

        if (final_layer && row0 + 256 <= NN) {
            #pragma unroll
            for (int i = 0; i < 2; i++)
                #pragma unroll
                for (int j = 0; j < 4; j++)
                    wmma::store_matrix_sync(foutv + (size_t)(row0 + 32 * wm + 16 * i) * DH + 64 * wn + 16 * j,
                                            acc[i][j], DH, wmma::mem_row_major);
            __syncthreads();
        } else {
            // smem roundtrip in 4 phases of 64 rows (scratch = A region, 64x132 f32)
            float* scr = reinterpret_cast<float*>(smem + OFF_A);
            #pragma unroll 1
            for (int hh = 0; hh < 4; hh++) {
                __syncthreads();
                if ((wm >> 1) == hh) {
                    int lr = 32 * (wm & 1);
                    #pragma unroll
                    for (int i = 0; i < 2; i++)
                        #pragma unroll
                        for (int j = 0; j < 4; j++)
                            wmma::store_matrix_sync(scr + (lr + 16 * i) * 132 + 64 * wn + 16 * j,
                                                    acc[i][j], 132, wmma::mem_row_major);
                }
                __syncthreads();
                int r6 = tid >> 3;      // 0..63
                int part = tid & 7;     // 16 elems
                int gr = row0 + hh * 64 + r6;
                if (gr < NN) {
                    const float* srow = scr + r6 * 132 + part * 16;
                    if (!final_layer) {
                        uint32_t hp[8], lp[8];
                        #pragma unroll
                        for (int q = 0; q < 8; q++) {
                            __half h0, l0, h1, l1;
                            split_h(srow[2 * q], h0, l0);
                            split_h(srow[2 * q + 1], h1, l1);
                            hp[q] = hpack(h0, h1);
                            lp[q] = hpack(l0, l1);
                        }
                        size_t off = (size_t)gr * DH + part * 16;
                        *reinterpret_cast<uint4*>(outhi + off)     = *reinterpret_cast<uint4*>(hp);
                        *reinterpret_cast<uint4*>(outhi + off + 8) = *reinterpret_cast<uint4*>(hp + 4);
                        *reinterpret_cast<uint4*>(outlo + off)     = *reinterpret_cast<uint4*>(lp);
                        *reinterpret_cast<uint4*>(outlo + off + 8) = *reinterpret_cast<uint4*>(lp + 4);
                    } else {
                        float* drow = foutv + (size_t)gr * DH + part * 16;
                        #pragma unroll
                        for (int q = 0; q < 4; q++)
                            *reinterpret_cast<float4*>(drow + q * 4) =
                                *reinterpret_cast<const float4*>(srow + q * 4);
                    }
                }
            }
            __syncthreads();   // scratch becomes A ring again next tile
        }
    }
}

// ============ host ============
extern "C" void kernel_launch(void* const* d_in, const int* in_sizes, int n_in,
                              void* d_out, int out_size) {
    const float* x      = (const float*)d_in[0];
    const int*   ei     = (const int*)d_in[1];
    const float* ea     = (const float*)d_in[2];
    const float* Wrel1  = (const float*)d_in[3];
    const float* b1     = (const float*)d_in[4];
    const float* Wroot1 = (const float*)d_in[5];
    const float* Wrel2  = (const float*)d_in[6];
    const float* b2     = (const float*)d_in[7];
    const float* Wroot2 = (const float*)d_in[8];
    const float* Wrel3  = (const float*)d_in[9];
    const float* b3     = (const float*)d_in[10];
    const float* Wroot3 = (const float*)d_in[11];
    float* out = (float*)d_out;

    const int* src = ei;
    const int* dst = ei + NE;

    int *deg, *rowptr, *cursor;
    uint2 *csr;
    __half *agghi, *agglo, *xhi, *xlo, *h1hi, *h1lo, *h2hi, *h2lo, *whi;
    cudaGetSymbolAddress((void**)&deg,    g_deg);
    cudaGetSymbolAddress((void**)&rowptr, g_rowptr);
    cudaGetSymbolAddress((void**)&cursor, g_cursor);
    cudaGetSymbolAddress((void**)&csr,    g_csr);
    cudaGetSymbolAddress((void**)&agghi,  g_agghi);
    cudaGetSymbolAddress((void**)&agglo,  g_agglo);
    cudaGetSymbolAddress((void**)&xhi,    g_xhi);
    cudaGetSymbolAddress((void**)&xlo,    g_xlo);
    cudaGetSymbolAddress((void**)&h1hi,   g_h1hi);
    cudaGetSymbolAddress((void**)&h1lo,   g_h1lo);
    cudaGetSymbolAddress((void**)&h2hi,   g_h2hi);
    cudaGetSymbolAddress((void**)&h2lo,   g_h2lo);
    cudaGetSymbolAddress((void**)&whi,    g_whi);

    cudaFuncSetAttribute(gemm_persist_kernel,
                         cudaFuncAttributeMaxDynamicSharedMemorySize, GEMM_SMEM);

    int prep_items = XQUADS + NN + WELEMS;
    prep_all_kernel<<<(prep_items + 255) / 256, 256>>>(
        x, Wrel1, Wroot1, Wrel2, Wroot2, Wrel3, Wroot3,
        xhi, xlo, whi, deg);
    deg_count_kernel<<<(NE + 255) / 256, 256>>>(dst, deg);
    scan_kernel<<<1, 1024>>>(deg, rowptr, cursor);
    fill_csr_kernel<<<(NE + 255) / 256, 256>>>(src, dst, ea, cursor, csr);

    const __half* inhi[3] = {xhi, h1hi, h2hi};
    const __half* inlo[3] = {xlo, h1lo, h2lo};
    __half* ohi[3] = {h1hi, h2hi, nullptr};
    __half* olo[3] = {h1lo, h2lo, nullptr};
    const float* bv[3] = {b1, b2, b3};

    int gather_blocks = (NN * 32 + 255) / 256;
    for (int l = 0; l < 3; l++) {
        gather_agg_kernel<<<gather_blocks, 256>>>(inhi[l], inlo[l], rowptr, csr, agghi, agglo);
        gemm_persist_kernel<<<148, 512, GEMM_SMEM>>>(
            agghi, agglo, inhi[l], inlo[l],
            whi + l * 32768, bv[l],
            ohi[l], olo[l], out, l == 2 ? 1 : 0);
    }
}

// round 13
// speedup vs baseline: 1.5886x; 1.2743x over previous
#include <cuda_runtime.h>
#include <cuda_fp16.h>
#include <mma.h>
#include <stdint.h>

using namespace nvcuda;

#define NN 100000
#define NE 1600000
#define DH 128
#define NT256 391    // ceil(NN/256)

// ---- scratch (device globals; no allocation allowed) ----
__device__ int   g_deg[NN];
__device__ int   g_rowptr[NN + 1];
__device__ int   g_cursor[NN];
__device__ uint2 g_csr[NE];
__device__ __half g_agg[NN * DH];
__device__ __half g_x16[NN * DH];
__device__ __half g_h1[NN * DH];
__device__ __half g_h2[NN * DH];
__device__ __half g_w16[3 * 256 * 128];   // [layer][k][n] fp16

// ============ small helpers ============
__device__ __forceinline__ uint32_t hpack(__half a, __half b) {
    return (uint32_t)__half_as_ushort(a) | ((uint32_t)__half_as_ushort(b) << 16);
}
__device__ __forceinline__ void split_h(float v, __half& h, __half& l) {
    h = __float2half_rn(v);
    l = __float2half_rn(v - __half2float(h));
}
__device__ __forceinline__ float2 h2f2(uint32_t u) {
    __half2 b = *reinterpret_cast<__half2*>(&u);
    return __half22float2(b);
}

// ============ fused prep: zero deg + convert x + convert weights ============
#define XQUADS (NN * DH / 4)
#define WELEMS (3 * 256 * 128)
__global__ void prep_all_kernel(const float* __restrict__ x,
                                const float* __restrict__ Wrel1, const float* __restrict__ Wroot1,
                                const float* __restrict__ Wrel2, const float* __restrict__ Wroot2,
                                const float* __restrict__ Wrel3, const float* __restrict__ Wroot3,
                                __half* __restrict__ x16, __half* __restrict__ w16,
                                int* __restrict__ deg) {
    int i = blockIdx.x * blockDim.x + threadIdx.x;
    if (i < XQUADS) {
        float4 v = *reinterpret_cast<const float4*>(x + (size_t)i * 4);
        uint2 p = make_uint2(hpack(__float2half_rn(v.x), __float2half_rn(v.y)),
                             hpack(__float2half_rn(v.z), __float2half_rn(v.w)));
        *reinterpret_cast<uint2*>(x16 + (size_t)i * 4) = p;
    } else if (i < XQUADS + NN) {
        deg[i - XQUADS] = 0;
    } else if (i < XQUADS + NN + WELEMS) {
        int w = i - (XQUADS + NN);
        int l = w >> 15;
        int j = w & 32767;
        int k = j >> 7, n = j & 127;
        const float* Wrel  = (l == 0) ? Wrel1  : (l == 1) ? Wrel2  : Wrel3;
        const float* Wroot = (l == 0) ? Wroot1 : (l == 1) ? Wroot2 : Wroot3;
        float v = (k < 128) ? Wrel[k * 128 + n] : Wroot[(k - 128) * 128 + n];
        w16[w] = __float2half_rn(v);
    }
}

// ============ CSR build ============
__global__ void deg_count_kernel(const int* __restrict__ dst, int* __restrict__ deg) {
    int i = blockIdx.x * blockDim.x + threadIdx.x;
    if (i < NE) atomicAdd(&deg[dst[i]], 1);
}

__global__ void scan_kernel(const int* __restrict__ deg,
                            int* __restrict__ rowptr, int* __restrict__ cursor) {
    __shared__ int wsum[32];
    __shared__ int carry;
    const int tid = threadIdx.x, lane = tid & 31, warp = tid >> 5;
    if (tid == 0) carry = 0;
    __syncthreads();
    for (int base = 0; base < NN; base += 1024) {
        int i = base + tid;
        int v = (i < NN) ? deg[i] : 0;
        int s = v;
        #pragma unroll
        for (int off = 1; off < 32; off <<= 1) {
            int t = __shfl_up_sync(0xFFFFFFFF, s, off);
            if (lane >= off) s += t;
        }
        if (lane == 31) wsum[warp] = s;
        __syncthreads();
        if (warp == 0) {
            int w = wsum[lane];
            #pragma unroll
            for (int off = 1; off < 32; off <<= 1) {
                int t = __shfl_up_sync(0xFFFFFFFF, w, off);
                if (lane >= off) w += t;
            }
            wsum[lane] = w;
        }
        __syncthreads();
        int excl = s - v + (warp > 0 ? wsum[warp - 1] : 0) + carry;
        if (i < NN) { rowptr[i] = excl; cursor[i] = excl; }
        __syncthreads();
        if (tid == 0) carry += wsum[31];
        __syncthreads();
    }
    if (threadIdx.x == 0) rowptr[NN] = carry;
}

__global__ void fill_csr_kernel(const int* __restrict__ src, const int* __restrict__ dst,
                                const float* __restrict__ w, int* __restrict__ cursor,
                                uint2* __restrict__ csr) {
    int e = blockIdx.x * blockDim.x + threadIdx.x;
    if (e < NE) {
        int d = dst[e];
        int p = atomicAdd(&cursor[d], 1);
        csr[p] = make_uint2((unsigned)src[e], __float_as_uint(w[e]));
    }
}

// ============ aggregation: one warp per node; single fp16 plane ============
__global__ void gather_agg_kernel(const __half* __restrict__ in16,
                                  const int* __restrict__ rowptr,
                                  const uint2* __restrict__ csr,
                                  __half* __restrict__ agg) {
    unsigned gt = blockIdx.x * blockDim.x + threadIdx.x;
    unsigned node = gt >> 5;
    int lane = threadIdx.x & 31;
    if (node >= NN) return;
    int s0 = __ldg(rowptr + node);
    int s1 = __ldg(rowptr + node + 1);
    float4 acc = make_float4(0.f, 0.f, 0.f, 0.f);
    int e = s0;
    for (; e + 3 < s1; e += 4) {
        uint2 e_[4];
        #pragma unroll
        for (int q = 0; q < 4; q++) e_[q] = __ldg(csr + e + q);
        uint2 v_[4];
        #pragma unroll
        for (int q = 0; q < 4; q++)
            v_[q] = *reinterpret_cast<const uint2*>(in16 + (size_t)e_[q].x * DH + lane * 4);
        #pragma unroll
        for (int q = 0; q < 4; q++) {
            float w0 = __uint_as_float(e_[q].y);
            float2 a = h2f2(v_[q].x), b = h2f2(v_[q].y);
            acc.x = fmaf(w0, a.x, acc.x); acc.y = fmaf(w0, a.y, acc.y);
            acc.z = fmaf(w0, b.x, acc.z); acc.w = fmaf(w0, b.y, acc.w);
        }
    }
    for (; e < s1; e++) {
        uint2 e0 = __ldg(csr + e);
        uint2 v0 = *reinterpret_cast<const uint2*>(in16 + (size_t)e0.x * DH + lane * 4);
        float w0 = __uint_as_float(e0.y);
        float2 a = h2f2(v0.x), b = h2f2(v0.y);
        acc.x = fmaf(w0, a.x, acc.x); acc.y = fmaf(w0, a.y, acc.y);
        acc.z = fmaf(w0, b.x, acc.z); acc.w = fmaf(w0, b.y, acc.w);
    }
    float di = (s1 > s0) ? 1.0f / (float)(s1 - s0) : 0.f;
    acc.x *= di; acc.y *= di; acc.z *= di; acc.w *= di;

    uint2 p = make_uint2(hpack(__float2half_rn(acc.x), __float2half_rn(acc.y)),
                         hpack(__float2half_rn(acc.z), __float2half_rn(acc.w)));
    *reinterpret_cast<uint2*>(agg + (size_t)node * DH + lane * 4) = p;
}

// ============ persistent wmma GEMM: 256x128 tiles, single-product fp16 ============
// 16 warps as 8(row)x2(col); warp tile 32x64, acc[2][4]. B fp16 plane resident.
// A: 16 chunks of 256x16 fp16, 3-stage cp.async ring, 1 cp.async per thread per chunk.
#define BSTR 136
#define ASTR 24
#define OFF_BH 0u                            // 256 x BSTR x 2 = 69632
#define OFF_BB 69632u                        // bias B: 16 x BSTR x 2 = 4352
#define OFF_AB 73984u                        // bias A: 16 x ASTR x 2 = 768
#define OFF_A  74752u                        // 3 stages x 12288
#define ASTAGE 12288u
#define GEMM_SMEM (74752 + 3 * 12288)        // 111616

__global__ void __launch_bounds__(512, 1) gemm_persist_kernel(
    const __half* __restrict__ agg, const __half* __restrict__ xin,
    const __half* __restrict__ w16,
    const float* __restrict__ bias,
    __half* __restrict__ outh, float* __restrict__ foutv, int final_layer)
{
    extern __shared__ char smem[];
    __half* BH = reinterpret_cast<__half*>(smem + OFF_BH);
    __half* BB = reinterpret_cast<__half*>(smem + OFF_BB);
    __half* AB = reinterpret_cast<__half*>(smem + OFF_AB);
    uint32_t smemA;
    {
        uint32_t a;
        asm("{ .reg .u64 t; cvta.to.shared.u64 t, %1; cvt.u32.u64 %0, t; }" : "=r"(a) : "l"(smem + OFF_A));
        smemA = a;
    }

    const int tid = threadIdx.x;
    const int wid = tid >> 5;
    const int wm = wid >> 1;      // 0..7 -> rows 32*wm
    const int wn = wid & 1;       // 0..1 -> cols 64*wn

    // one-time staging: B plane + bias chunks
    #pragma unroll
    for (int j = 0; j < 8; j++) {
        int f = tid + j * 512;
        int rr = f >> 4, c8 = f & 15;
        uint4 vh = *reinterpret_cast<const uint4*>(w16 + (size_t)rr * 128 + c8 * 8);
        *reinterpret_cast<uint4*>(BH + rr * BSTR + c8 * 8) = vh;
    }
    for (int i = tid; i < (16 * BSTR + 16 * ASTR) / 2; i += 512)
        reinterpret_cast<uint32_t*>(BB)[i] = 0;   // BB then AB contiguous
    __syncthreads();
    if (tid < 128) {
        __half h, l;
        split_h(bias[tid], h, l);
        BB[0 * BSTR + tid] = h;
        BB[1 * BSTR + tid] = l;
        if (tid < 16) {
            AB[tid * ASTR + 0] = __float2half_rn(1.0f);
            AB[tid * ASTR + 1] = __float2half_rn(1.0f);
        }
    }
    __syncthreads();

    for (int tile = blockIdx.x; tile < NT256; tile += 148) {
        const int row0 = tile * 256;
        const int arow = tid >> 1;            // 0..255
        const int aseg = tid & 1;             // 8 fp16 = 16B each
        const int grow = row0 + arow;
        const int sz = (grow < NN) ? 16 : 0;

        auto issue = [&](int c) {
            const __half* p = (c < 8) ? agg : xin;
            const int k0 = (c & 7) * 16;
            const __half* s = p + (size_t)grow * DH + k0 + aseg * 8;
            uint32_t d = smemA + (uint32_t)(c % 3) * ASTAGE + (uint32_t)(arow * ASTR + aseg * 8) * 2u;
            asm volatile("cp.async.cg.shared.global [%0], [%1], 16, %2;" :: "r"(d), "l"(s), "r"(sz));
            asm volatile("cp.async.commit_group;");
        };

        wmma::fragment<wmma::accumulator, 16, 16, 16, float> acc[2][4];
        #pragma unroll
        for (int i = 0; i < 2; i++)
            #pragma unroll
            for (int j = 0; j < 4; j++) wmma::fill_fragment(acc[i][j], 0.f);

        // bias rank-1 chunk
        {
            wmma::fragment<wmma::matrix_a, 16, 16, 16, __half, wmma::row_major> fa;
            wmma::load_matrix_sync(fa, AB, ASTR);
            #pragma unroll
            for (int j = 0; j < 4; j++) {
                wmma::fragment<wmma::matrix_b, 16, 16, 16, __half, wmma::row_major> fb;
                wmma::load_matrix_sync(fb, BB + 64 * wn + 16 * j, BSTR);
                #pragma unroll
                for (int i = 0; i < 2; i++)
                    wmma::mma_sync(acc[i][j], fa, fb, acc[i][j]);
            }
        }

        issue(0);
        issue(1);

        #pragma unroll 1
        for (int c = 0; c < 16; c++) {
            if (c < 14) {
                issue(c + 2);
                asm volatile("cp.async.wait_group 2;");
            } else if (c == 14) {
                asm volatile("cp.async.wait_group 1;");
            } else {
                asm volatile("cp.async.wait_group 0;");
            }
            __syncthreads();
            const __half* Ac = reinterpret_cast<const __half*>(smem + OFF_A + (c % 3) * ASTAGE);
            const int krow = c * 16;
            wmma::fragment<wmma::matrix_b, 16, 16, 16, __half, wmma::row_major> fbh[4];
            #pragma unroll
            for (int j = 0; j < 4; j++)
                wmma::load_matrix_sync(fbh[j], BH + krow * BSTR + 64 * wn + 16 * j, BSTR);
            #pragma unroll
            for (int i = 0; i < 2; i++) {
                wmma::fragment<wmma::matrix_a, 16, 16, 16, __half, wmma::row_major> fah;
                wmma::load_matrix_sync(fah, Ac + (32 * wm + 16 * i) * ASTR, ASTR);
                #pragma unroll
                for (int j = 0; j < 4; j++)
                    wmma::mma_sync(acc[i][j], fah, fbh[j], acc[i][j]);
            }
            __syncthreads();   // stage consumed before refill (ring distance 3 guarded by wait_group)
        }

        // relu
        #pragma unroll
        for (int i = 0; i < 2; i++)
            #pragma unroll
            for (int j = 0; j < 4; j++)
                #pragma unroll
                for (int e = 0; e < acc[i][j].num_elements; e++)
                    acc[i][j].x[e] = fmaxf(acc[i][j].x[e], 0.f);

        if (final_layer && row0 + 256 <= NN) {
            #pragma unroll
            for (int i = 0; i < 2; i++)
                #pragma unroll
                for (int j = 0; j < 4; j++)
                    wmma::store_matrix_sync(foutv + (size_t)(row0 + 32 * wm + 16 * i) * DH + 64 * wn + 16 * j,
                                            acc[i][j], DH, wmma::mem_row_major);
            __syncthreads();
        } else {
            // smem roundtrip in 4 phases of 64 rows (scratch = A region, 64x132 f32 = 33792 <= 36864)
            float* scr = reinterpret_cast<float*>(smem + OFF_A);
            #pragma unroll 1
            for (int hh = 0; hh < 4; hh++) {
                __syncthreads();
                if ((wm >> 1) == hh) {
                    int lr = 32 * (wm & 1);
                    #pragma unroll
                    for (int i = 0; i < 2; i++)
                        #pragma unroll
                        for (int j = 0; j < 4; j++)
                            wmma::store_matrix_sync(scr + (lr + 16 * i) * 132 + 64 * wn + 16 * j,
                                                    acc[i][j], 132, wmma::mem_row_major);
                }
                __syncthreads();
                int r6 = tid >> 3;      // 0..63
                int part = tid & 7;     // 16 elems
                int gr = row0 + hh * 64 + r6;
                if (gr < NN) {
                    const float* srow = scr + r6 * 132 + part * 16;
                    if (!final_layer) {
                        uint32_t hp[8];
                        #pragma unroll
                        for (int q = 0; q < 8; q++)
                            hp[q] = hpack(__float2half_rn(srow[2 * q]), __float2half_rn(srow[2 * q + 1]));
                        size_t off = (size_t)gr * DH + part * 16;
                        *reinterpret_cast<uint4*>(outh + off)     = *reinterpret_cast<uint4*>(hp);
                        *reinterpret_cast<uint4*>(outh + off + 8) = *reinterpret_cast<uint4*>(hp + 4);
                    } else {
                        float* drow = foutv + (size_t)gr * DH + part * 16;
                        #pragma unroll
                        for (int q = 0; q < 4; q++)
                            *reinterpret_cast<float4*>(drow + q * 4) =
                                *reinterpret_cast<const float4*>(srow + q * 4);
                    }
                }
            }
            __syncthreads();   // scratch becomes A ring again next tile
        }
    }
}

// ============ host ============
extern "C" void kernel_launch(void* const* d_in, const int* in_sizes, int n_in,
                              void* d_out, int out_size) {
    const float* x      = (const float*)d_in[0];
    const int*   ei     = (const int*)d_in[1];
    const float* ea     = (const float*)d_in[2];
    const float* Wrel1  = (const float*)d_in[3];
    const float* b1     = (const float*)d_in[4];
    const float* Wroot1 = (const float*)d_in[5];
    const float* Wrel2  = (const float*)d_in[6];
    const float* b2     = (const float*)d_in[7];
    const float* Wroot2 = (const float*)d_in[8];
    const float* Wrel3  = (const float*)d_in[9];
    const float* b3     = (const float*)d_in[10];
    const float* Wroot3 = (const float*)d_in[11];
    float* out = (float*)d_out;

    const int* src = ei;
    const int* dst = ei + NE;

    int *deg, *rowptr, *cursor;
    uint2 *csr;
    __half *agg, *x16, *h1, *h2, *w16;
    cudaGetSymbolAddress((void**)&deg,    g_deg);
    cudaGetSymbolAddress((void**)&rowptr, g_rowptr);
    cudaGetSymbolAddress((void**)&cursor, g_cursor);
    cudaGetSymbolAddress((void**)&csr,    g_csr);
    cudaGetSymbolAddress((void**)&agg,    g_agg);
    cudaGetSymbolAddress((void**)&x16,    g_x16);
    cudaGetSymbolAddress((void**)&h1,     g_h1);
    cudaGetSymbolAddress((void**)&h2,     g_h2);
    cudaGetSymbolAddress((void**)&w16,    g_w16);

    cudaFuncSetAttribute(gemm_persist_kernel,
                         cudaFuncAttributeMaxDynamicSharedMemorySize, GEMM_SMEM);

    int prep_items = XQUADS + NN + WELEMS;
    prep_all_kernel<<<(prep_items + 255) / 256, 256>>>(
        x, Wrel1, Wroot1, Wrel2, Wroot2, Wrel3, Wroot3,
        x16, w16, deg);
    deg_count_kernel<<<(NE + 255) / 256, 256>>>(dst, deg);
    scan_kernel<<<1, 1024>>>(deg, rowptr, cursor);
    fill_csr_kernel<<<(NE + 255) / 256, 256>>>(src, dst, ea, cursor, csr);

    const __half* in16[3] = {x16, h1, h2};
    __half* oh[3] = {h1, h2, nullptr};
    const float* bv[3] = {b1, b2, b3};

    int gather_blocks = (NN * 32 + 255) / 256;
    for (int l = 0; l < 3; l++) {
        gather_agg_kernel<<<gather_blocks, 256>>>(in16[l], rowptr, csr, agg);
        gemm_persist_kernel<<<148, 512, GEMM_SMEM>>>(
            agg, in16[l], w16 + l * 32768, bv[l],
            oh[l], out, l == 2 ? 1 : 0);
    }
}

// round 14
// speedup vs baseline: 1.6339x; 1.0285x over previous
#include <cuda_runtime.h>
#include <cuda_fp16.h>
#include <mma.h>
#include <stdint.h>

using namespace nvcuda;

#define NN 100000
#define NE 1600000
#define DH 128
#define NT256 391    // ceil(NN/256)

// ---- scratch (device globals; no allocation allowed) ----
__device__ int   g_deg[NN];
__device__ int   g_rowptr[NN + 1];
__device__ int   g_cursor[NN];
__device__ uint2 g_csr[NE];
__device__ __half g_agg[NN * DH];
__device__ __half g_x16[NN * DH];
__device__ __half g_h1[NN * DH];
__device__ __half g_h2[NN * DH];
__device__ __half g_w16[3 * 256 * 128];   // [layer][k][n] fp16

// ============ small helpers ============
__device__ __forceinline__ uint32_t hpack(__half a, __half b) {
    return (uint32_t)__half_as_ushort(a) | ((uint32_t)__half_as_ushort(b) << 16);
}
__device__ __forceinline__ void split_h(float v, __half& h, __half& l) {
    h = __float2half_rn(v);
    l = __float2half_rn(v - __half2float(h));
}
__device__ __forceinline__ float2 h2f2(uint32_t u) {
    __half2 b = *reinterpret_cast<__half2*>(&u);
    return __half22float2(b);
}

// ============ fused prep: zero deg + convert x + convert weights ============
#define XQUADS (NN * DH / 4)
#define WELEMS (3 * 256 * 128)
__global__ void prep_all_kernel(const float* __restrict__ x,
                                const float* __restrict__ Wrel1, const float* __restrict__ Wroot1,
                                const float* __restrict__ Wrel2, const float* __restrict__ Wroot2,
                                const float* __restrict__ Wrel3, const float* __restrict__ Wroot3,
                                __half* __restrict__ x16, __half* __restrict__ w16,
                                int* __restrict__ deg) {
    int i = blockIdx.x * blockDim.x + threadIdx.x;
    if (i < XQUADS) {
        float4 v = *reinterpret_cast<const float4*>(x + (size_t)i * 4);
        uint2 p = make_uint2(hpack(__float2half_rn(v.x), __float2half_rn(v.y)),
                             hpack(__float2half_rn(v.z), __float2half_rn(v.w)));
        *reinterpret_cast<uint2*>(x16 + (size_t)i * 4) = p;
    } else if (i < XQUADS + NN) {
        deg[i - XQUADS] = 0;
    } else if (i < XQUADS + NN + WELEMS) {
        int w = i - (XQUADS + NN);
        int l = w >> 15;
        int j = w & 32767;
        int k = j >> 7, n = j & 127;
        const float* Wrel  = (l == 0) ? Wrel1  : (l == 1) ? Wrel2  : Wrel3;
        const float* Wroot = (l == 0) ? Wroot1 : (l == 1) ? Wroot2 : Wroot3;
        float v = (k < 128) ? Wrel[k * 128 + n] : Wroot[(k - 128) * 128 + n];
        w16[w] = __float2half_rn(v);
    }
}

// ============ CSR build ============
__global__ void deg_count_kernel(const int* __restrict__ dst, int* __restrict__ deg) {
    int i = blockIdx.x * blockDim.x + threadIdx.x;
    if (i < NE) atomicAdd(&deg[dst[i]], 1);
}

__global__ void scan_kernel(const int* __restrict__ deg,
                            int* __restrict__ rowptr, int* __restrict__ cursor) {
    __shared__ int wsum[32];
    __shared__ int carry;
    const int tid = threadIdx.x, lane = tid & 31, warp = tid >> 5;
    if (tid == 0) carry = 0;
    __syncthreads();
    for (int base = 0; base < NN; base += 1024) {
        int i = base + tid;
        int v = (i < NN) ? deg[i] : 0;
        int s = v;
        #pragma unroll
        for (int off = 1; off < 32; off <<= 1) {
            int t = __shfl_up_sync(0xFFFFFFFF, s, off);
            if (lane >= off) s += t;
        }
        if (lane == 31) wsum[warp] = s;
        __syncthreads();
        if (warp == 0) {
            int w = wsum[lane];
            #pragma unroll
            for (int off = 1; off < 32; off <<= 1) {
                int t = __shfl_up_sync(0xFFFFFFFF, w, off);
                if (lane >= off) w += t;
            }
            wsum[lane] = w;
        }
        __syncthreads();
        int excl = s - v + (warp > 0 ? wsum[warp - 1] : 0) + carry;
        if (i < NN) { rowptr[i] = excl; cursor[i] = excl; }
        __syncthreads();
        if (tid == 0) carry += wsum[31];
        __syncthreads();
    }
    if (threadIdx.x == 0) rowptr[NN] = carry;
}

__global__ void fill_csr_kernel(const int* __restrict__ src, const int* __restrict__ dst,
                                const float* __restrict__ w, int* __restrict__ cursor,
                                uint2* __restrict__ csr) {
    int e = blockIdx.x * blockDim.x + threadIdx.x;
    if (e < NE) {
        int d = dst[e];
        int p = atomicAdd(&cursor[d], 1);
        csr[p] = make_uint2((unsigned)src[e], __float_as_uint(w[e]));
    }
}

// ============ aggregation: one warp per node; single fp16 plane ============
__global__ void gather_agg_kernel(const __half* __restrict__ in16,
                                  const int* __restrict__ rowptr,
                                  const uint2* __restrict__ csr,
                                  __half* __restrict__ agg) {
    unsigned gt = blockIdx.x * blockDim.x + threadIdx.x;
    unsigned node = gt >> 5;
    int lane = threadIdx.x & 31;
    if (node >= NN) return;
    int s0 = __ldg(rowptr + node);
    int s1 = __ldg(rowptr + node + 1);
    float4 acc = make_float4(0.f, 0.f, 0.f, 0.f);
    int e = s0;
    for (; e + 3 < s1; e += 4) {
        uint2 e_[4];
        #pragma unroll
        for (int q = 0; q < 4; q++) e_[q] = __ldg(csr + e + q);
        uint2 v_[4];
        #pragma unroll
        for (int q = 0; q < 4; q++)
            v_[q] = *reinterpret_cast<const uint2*>(in16 + (size_t)e_[q].x * DH + lane * 4);
        #pragma unroll
        for (int q = 0; q < 4; q++) {
            float w0 = __uint_as_float(e_[q].y);
            float2 a = h2f2(v_[q].x), b = h2f2(v_[q].y);
            acc.x = fmaf(w0, a.x, acc.x); acc.y = fmaf(w0, a.y, acc.y);
            acc.z = fmaf(w0, b.x, acc.z); acc.w = fmaf(w0, b.y, acc.w);
        }
    }
    for (; e < s1; e++) {
        uint2 e0 = __ldg(csr + e);
        uint2 v0 = *reinterpret_cast<const uint2*>(in16 + (size_t)e0.x * DH + lane * 4);
        float w0 = __uint_as_float(e0.y);
        float2 a = h2f2(v0.x), b = h2f2(v0.y);
        acc.x = fmaf(w0, a.x, acc.x); acc.y = fmaf(w0, a.y, acc.y);
        acc.z = fmaf(w0, b.x, acc.z); acc.w = fmaf(w0, b.y, acc.w);
    }
    float di = (s1 > s0) ? 1.0f / (float)(s1 - s0) : 0.f;
    acc.x *= di; acc.y *= di; acc.z *= di; acc.w *= di;

    uint2 p = make_uint2(hpack(__float2half_rn(acc.x), __float2half_rn(acc.y)),
                         hpack(__float2half_rn(acc.z), __float2half_rn(acc.w)));
    *reinterpret_cast<uint2*>(agg + (size_t)node * DH + lane * 4) = p;
}

// ============ persistent wmma GEMM: 256x128 tiles, single-product fp16 ============
// 16 warps as 8(row)x2(col); warp tile 32x64, acc[2][4]. B fp16 plane resident.
// A: 8 chunks of 256x32 fp16, 3-stage cp.async ring, ONE barrier per chunk.
#define BSTR 136
#define ASTR 24                              // bias A chunk stride
#define ASTR2 40                             // A ring stride (32 halves + 8 pad)
#define OFF_BH 0u                            // 256 x BSTR x 2 = 69632
#define OFF_BB 69632u                        // bias B: 16 x BSTR x 2 = 4352
#define OFF_AB 73984u                        // bias A: 16 x ASTR x 2 = 768
#define OFF_A  74752u                        // 3 stages x 20480
#define ASTAGE 20480u
#define GEMM_SMEM (74752 + 3 * 20480)        // 136192

__global__ void __launch_bounds__(512, 1) gemm_persist_kernel(
    const __half* __restrict__ agg, const __half* __restrict__ xin,
    const __half* __restrict__ w16,
    const float* __restrict__ bias,
    __half* __restrict__ outh, float* __restrict__ foutv, int final_layer)
{
    extern __shared__ char smem[];
    __half* BH = reinterpret_cast<__half*>(smem + OFF_BH);
    __half* BB = reinterpret_cast<__half*>(smem + OFF_BB);
    __half* AB = reinterpret_cast<__half*>(smem + OFF_AB);
    uint32_t smemA;
    {
        uint32_t a;
        asm("{ .reg .u64 t; cvta.to.shared.u64 t, %1; cvt.u32.u64 %0, t; }" : "=r"(a) : "l"(smem + OFF_A));
        smemA = a;
    }

    const int tid = threadIdx.x;
    const int wid = tid >> 5;
    const int wm = wid >> 1;      // 0..7 -> rows 32*wm
    const int wn = wid & 1;       // 0..1 -> cols 64*wn

    // one-time staging: B plane + bias chunks
    #pragma unroll
    for (int j = 0; j < 8; j++) {
        int f = tid + j * 512;
        int rr = f >> 4, c8 = f & 15;
        uint4 vh = *reinterpret_cast<const uint4*>(w16 + (size_t)rr * 128 + c8 * 8);
        *reinterpret_cast<uint4*>(BH + rr * BSTR + c8 * 8) = vh;
    }
    for (int i = tid; i < (16 * BSTR + 16 * ASTR) / 2; i += 512)
        reinterpret_cast<uint32_t*>(BB)[i] = 0;   // BB then AB contiguous
    __syncthreads();
    if (tid < 128) {
        __half h, l;
        split_h(bias[tid], h, l);
        BB[0 * BSTR + tid] = h;
        BB[1 * BSTR + tid] = l;
        if (tid < 16) {
            AB[tid * ASTR + 0] = __float2half_rn(1.0f);
            AB[tid * ASTR + 1] = __float2half_rn(1.0f);
        }
    }
    __syncthreads();

    for (int tile = blockIdx.x; tile < NT256; tile += 148) {
        const int row0 = tile * 256;
        const int arow = tid >> 1;            // 0..255
        const int aseg = tid & 1;             // 16 fp16 = 32B each
        const int grow = row0 + arow;
        const int sz = (grow < NN) ? 16 : 0;

        // chunk c in [0,8): k = c*32..c*32+31 ; c<4 agg, c>=4 xin
        auto issue = [&](int c) {
            const __half* p = (c < 4) ? agg : xin;
            const int k0 = (c & 3) * 32;
            const __half* s = p + (size_t)grow * DH + k0 + aseg * 16;
            uint32_t d = smemA + (uint32_t)(c % 3) * ASTAGE + (uint32_t)(arow * ASTR2 + aseg * 16) * 2u;
            asm volatile("cp.async.cg.shared.global [%0], [%1], 16, %2;" :: "r"(d), "l"(s), "r"(sz));
            asm volatile("cp.async.cg.shared.global [%0], [%1], 16, %2;" :: "r"(d + 16u), "l"(s + 8), "r"(sz));
            asm volatile("cp.async.commit_group;");
        };

        wmma::fragment<wmma::accumulator, 16, 16, 16, float> acc[2][4];
        #pragma unroll
        for (int i = 0; i < 2; i++)
            #pragma unroll
            for (int j = 0; j < 4; j++) wmma::fill_fragment(acc[i][j], 0.f);

        // bias rank-1 chunk
        {
            wmma::fragment<wmma::matrix_a, 16, 16, 16, __half, wmma::row_major> fa;
            wmma::load_matrix_sync(fa, AB, ASTR);
            #pragma unroll
            for (int j = 0; j < 4; j++) {
                wmma::fragment<wmma::matrix_b, 16, 16, 16, __half, wmma::row_major> fb;
                wmma::load_matrix_sync(fb, BB + 64 * wn + 16 * j, BSTR);
                #pragma unroll
                for (int i = 0; i < 2; i++)
                    wmma::mma_sync(acc[i][j], fa, fb, acc[i][j]);
            }
        }

        issue(0);
        issue(1);

        // ONE barrier per chunk: wait -> barrier -> issue(c+2) -> compute(c).
        // The barrier certifies all warps finished chunk c-1, so refilling
        // buffer (c+2)%3 == (c-1)%3 afterwards is race-free.
        #pragma unroll 1
        for (int c = 0; c < 8; c++) {
            if (c < 7) asm volatile("cp.async.wait_group 1;");
            else       asm volatile("cp.async.wait_group 0;");
            __syncthreads();
            if (c < 6) issue(c + 2);

            const __half* Ac = reinterpret_cast<const __half*>(smem + OFF_A + (c % 3) * ASTAGE);
            #pragma unroll
            for (int kk = 0; kk < 2; kk++) {
                const int krow = c * 32 + kk * 16;
                wmma::fragment<wmma::matrix_b, 16, 16, 16, __half, wmma::row_major> fbh[4];
                #pragma unroll
                for (int j = 0; j < 4; j++)
                    wmma::load_matrix_sync(fbh[j], BH + krow * BSTR + 64 * wn + 16 * j, BSTR);
                #pragma unroll
                for (int i = 0; i < 2; i++) {
                    wmma::fragment<wmma::matrix_a, 16, 16, 16, __half, wmma::row_major> fah;
                    wmma::load_matrix_sync(fah, Ac + (32 * wm + 16 * i) * ASTR2 + kk * 16, ASTR2);
                    #pragma unroll
                    for (int j = 0; j < 4; j++)
                        wmma::mma_sync(acc[i][j], fah, fbh[j], acc[i][j]);
                }
            }
        }

        // relu
        #pragma unroll
        for (int i = 0; i < 2; i++)
            #pragma unroll
            for (int j = 0; j < 4; j++)
                #pragma unroll
                for (int e = 0; e < acc[i][j].num_elements; e++)
                    acc[i][j].x[e] = fmaxf(acc[i][j].x[e], 0.f);

        if (final_layer && row0 + 256 <= NN) {
            __syncthreads();   // all warps done with A ring before next tile refill
            #pragma unroll
            for (int i = 0; i < 2; i++)
                #pragma unroll
                for (int j = 0; j < 4; j++)
                    wmma::store_matrix_sync(foutv + (size_t)(row0 + 32 * wm + 16 * i) * DH + 64 * wn + 16 * j,
                                            acc[i][j], DH, wmma::mem_row_major);
            __syncthreads();
        } else {
            // smem roundtrip in 4 phases of 64 rows (scratch = A region, 64x132 f32 = 33792 <= 61440)
            float* scr = reinterpret_cast<float*>(smem + OFF_A);
            #pragma unroll 1
            for (int hh = 0; hh < 4; hh++) {
                __syncthreads();
                if ((wm >> 1) == hh) {
                    int lr = 32 * (wm & 1);
                    #pragma unroll
                    for (int i = 0; i < 2; i++)
                        #pragma unroll
                        for (int j = 0; j < 4; j++)
                            wmma::store_matrix_sync(scr + (lr + 16 * i) * 132 + 64 * wn + 16 * j,
                                                    acc[i][j], 132, wmma::mem_row_major);
                }
                __syncthreads();
                int r6 = tid >> 3;      // 0..63
                int part = tid & 7;     // 16 elems
                int gr = row0 + hh * 64 + r6;
                if (gr < NN) {
                    const float* srow = scr + r6 * 132 + part * 16;
                    if (!final_layer) {
                        uint32_t hp[8];
                        #pragma unroll
                        for (int q = 0; q < 8; q++)
                            hp[q] = hpack(__float2half_rn(srow[2 * q]), __float2half_rn(srow[2 * q + 1]));
                        size_t off = (size_t)gr * DH + part * 16;
                        *reinterpret_cast<uint4*>(outh + off)     = *reinterpret_cast<uint4*>(hp);
                        *reinterpret_cast<uint4*>(outh + off + 8) = *reinterpret_cast<uint4*>(hp + 4);
                    } else {
                        float* drow = foutv + (size_t)gr * DH + part * 16;
                        #pragma unroll
                        for (int q = 0; q < 4; q++)
                            *reinterpret_cast<float4*>(drow + q * 4) =
                                *reinterpret_cast<const float4*>(srow + q * 4);
                    }
                }
            }
            __syncthreads();   // scratch becomes A ring again next tile
        }
    }
}

// ============ host ============
extern "C" void kernel_launch(void* const* d_in, const int* in_sizes, int n_in,
                              void* d_out, int out_size) {
    const float* x      = (const float*)d_in[0];
    const int*   ei     = (const int*)d_in[1];
    const float* ea     = (const float*)d_in[2];
    const float* Wrel1  = (const float*)d_in[3];
    const float* b1     = (const float*)d_in[4];
    const float* Wroot1 = (const float*)d_in[5];
    const float* Wrel2  = (const float*)d_in[6];
    const float* b2     = (const float*)d_in[7];
    const float* Wroot2 = (const float*)d_in[8];
    const float* Wrel3  = (const float*)d_in[9];
    const float* b3     = (const float*)d_in[10];
    const float* Wroot3 = (const float*)d_in[11];
    float* out = (float*)d_out;

    const int* src = ei;
    const int* dst = ei + NE;

    int *deg, *rowptr, *cursor;
    uint2 *csr;
    __half *agg, *x16, *h1, *h2, *w16;
    cudaGetSymbolAddress((void**)&deg,    g_deg);
    cudaGetSymbolAddress((void**)&rowptr, g_rowptr);
    cudaGetSymbolAddress((void**)&cursor, g_cursor);
    cudaGetSymbolAddress((void**)&csr,    g_csr);
    cudaGetSymbolAddress((void**)&agg,    g_agg);
    cudaGetSymbolAddress((void**)&x16,    g_x16);
    cudaGetSymbolAddress((void**)&h1,     g_h1);
    cudaGetSymbolAddress((void**)&h2,     g_h2);
    cudaGetSymbolAddress((void**)&w16,    g_w16);

    cudaFuncSetAttribute(gemm_persist_kernel,
                         cudaFuncAttributeMaxDynamicSharedMemorySize, GEMM_SMEM);

    int prep_items = XQUADS + NN + WELEMS;
    prep_all_kernel<<<(prep_items + 255) / 256, 256>>>(
        x, Wrel1, Wroot1, Wrel2, Wroot2, Wrel3, Wroot3,
        x16, w16, deg);
    deg_count_kernel<<<(NE + 255) / 256, 256>>>(dst, deg);
    scan_kernel<<<1, 1024>>>(deg, rowptr, cursor);
    fill_csr_kernel<<<(NE + 255) / 256, 256>>>(src, dst, ea, cursor, csr);

    const __half* in16[3] = {x16, h1, h2};
    __half* oh[3] = {h1, h2, nullptr};
    const float* bv[3] = {b1, b2, b3};

    int gather_blocks = (NN * 32 + 255) / 256;
    for (int l = 0; l < 3; l++) {
        gather_agg_kernel<<<gather_blocks, 256>>>(in16[l], rowptr, csr, agg);
        gemm_persist_kernel<<<148, 512, GEMM_SMEM>>>(
            agg, in16[l], w16 + l * 32768, bv[l],
            oh[l], out, l == 2 ? 1 : 0);
    }
}